// round 5
// baseline (speedup 1.0000x reference)
#include <cuda_runtime.h>
#include <cuda_bf16.h>
#include <math.h>
#include <stdint.h>

#define BBATCH 16
#define SSEQ   2048
#define EMB    768
#define NHEAD  8
#define DHEAD  96
#define MROWS  (BBATCH*SSEQ)   // 32768
#define KDIM   768
#define NCH    24              // 768 / BK, BK=32

// ---------------- scratch (device globals; allocation-free rule) -----------
__device__ float          g_qkv[(size_t)MROWS*2304];
__device__ __nv_bfloat16  g_fhi[(size_t)MROWS*KDIM];
__device__ __nv_bfloat16  g_flo[(size_t)MROWS*KDIM];
__device__ __nv_bfloat16  g_chi[(size_t)MROWS*KDIM];
__device__ __nv_bfloat16  g_clo[(size_t)MROWS*KDIM];
__device__ __nv_bfloat16  g_ohi[(size_t)MROWS*KDIM];
__device__ __nv_bfloat16  g_olo[(size_t)MROWS*KDIM];
__device__ float          g_hbuf[(size_t)MROWS*384];
__device__ __nv_bfloat16  g_whi[(size_t)(2304+768+384)*KDIM];
__device__ __nv_bfloat16  g_wlo[(size_t)(2304+768+384)*KDIM];

// ---------------- helpers ---------------------------------------------------
__device__ __forceinline__ uint32_t s2u(const void* p){
    uint32_t a;
    asm("{ .reg .u64 t; cvta.to.shared.u64 t, %1; cvt.u32.u64 %0, t; }":"=r"(a):"l"(p));
    return a;
}
#define SWZ(o) ((o) ^ (((o) >> 3) & 0x70))
#define CP16(s, g) asm volatile("cp.async.cg.shared.global [%0], [%1], 16;"::"r"(s),"l"(g):"memory")

__device__ __forceinline__ void mma16816(float* c, const uint32_t* a, uint32_t b0, uint32_t b1){
    asm volatile("mma.sync.aligned.m16n8k16.row.col.f32.bf16.bf16.f32 "
        "{%0,%1,%2,%3},{%4,%5,%6,%7},{%8,%9},{%0,%1,%2,%3};"
        : "+f"(c[0]), "+f"(c[1]), "+f"(c[2]), "+f"(c[3])
        : "r"(a[0]), "r"(a[1]), "r"(a[2]), "r"(a[3]), "r"(b0), "r"(b1));
}

__device__ __forceinline__ void split_one(float x, __nv_bfloat16& h, __nv_bfloat16& l){
    h = __float2bfloat16(x);
    l = __float2bfloat16(x - __bfloat162float(h));
}

// ---------------- fp32 -> bf16 hi/lo split (vectorized x4) -----------------
__global__ __launch_bounds__(256)
void split4(const float* __restrict__ src, __nv_bfloat16* __restrict__ hi,
            __nv_bfloat16* __restrict__ lo, size_t n4){
    size_t i = (size_t)blockIdx.x * blockDim.x + threadIdx.x;
    if (i >= n4) return;
    float4 v = ((const float4*)src)[i];
    __nv_bfloat16 h0,h1,h2,h3,l0,l1,l2,l3;
    split_one(v.x,h0,l0); split_one(v.y,h1,l1);
    split_one(v.z,h2,l2); split_one(v.w,h3,l3);
    ((__nv_bfloat162*)hi)[2*i]   = __nv_bfloat162(h0,h1);
    ((__nv_bfloat162*)hi)[2*i+1] = __nv_bfloat162(h2,h3);
    ((__nv_bfloat162*)lo)[2*i]   = __nv_bfloat162(l0,l1);
    ((__nv_bfloat162*)lo)[2*i+1] = __nv_bfloat162(l2,l3);
}

// split two tensors in one launch (keeps gemm1 in profiled slot #4)
__global__ __launch_bounds__(256)
void split4x2(const float* __restrict__ sa, __nv_bfloat16* __restrict__ ha,
              __nv_bfloat16* __restrict__ la, size_t na4,
              const float* __restrict__ sb, __nv_bfloat16* __restrict__ hb,
              __nv_bfloat16* __restrict__ lb, size_t nb4){
    size_t i = (size_t)blockIdx.x * blockDim.x + threadIdx.x;
    const float* src; __nv_bfloat16 *hi, *lo;
    if (i < na4){ src = sa; hi = ha; lo = la; }
    else if (i < na4 + nb4){ i -= na4; src = sb; hi = hb; lo = lb; }
    else return;
    float4 v = ((const float4*)src)[i];
    __nv_bfloat16 h0,h1,h2,h3,l0,l1,l2,l3;
    split_one(v.x,h0,l0); split_one(v.y,h1,l1);
    split_one(v.z,h2,l2); split_one(v.w,h3,l3);
    ((__nv_bfloat162*)hi)[2*i]   = __nv_bfloat162(h0,h1);
    ((__nv_bfloat162*)hi)[2*i+1] = __nv_bfloat162(h2,h3);
    ((__nv_bfloat162*)lo)[2*i]   = __nv_bfloat162(l0,l1);
    ((__nv_bfloat162*)lo)[2*i+1] = __nv_bfloat162(l2,l3);
}

// ---------------- mma.sync GEMM, BM=256 BN=128 BK=32, 512 thr --------------
// 3-pass hi/lo split with shared loads: smem row = [hi 64B | lo 64B] (SW128).
// 3-stage cp.async ring (48KB/stage). 16 warps: 4m x 4n, warp tile 64x32.
// EPI: 0 fp32 out, 1 fp32+ReLU, 2 bf16 hi/lo planes out.
#define STG 49152u
template<int EPI>
__global__ __launch_bounds__(512, 1)
void gemm_mma(const __nv_bfloat16* __restrict__ Ahi, const __nv_bfloat16* __restrict__ Alo,
              const __nv_bfloat16* __restrict__ Bhi, const __nv_bfloat16* __restrict__ Blo,
              const float* __restrict__ bias, float* __restrict__ Cf,
              __nv_bfloat16* __restrict__ Chi, __nv_bfloat16* __restrict__ Clo, int N)
{
    extern __shared__ __align__(1024) char sm[];
    const int tid = threadIdx.x, lane = tid & 31, warp = tid >> 5;
    const int m0 = blockIdx.y * 256, n0 = blockIdx.x * 128;
    const int wm = (warp & 3) * 64, wn = (warp >> 2) * 32;
    const uint32_t sbase = s2u(sm);

    auto load_tile = [&](int t){
        const uint32_t st = sbase + (uint32_t)(t % 3) * STG;
        const int k0 = t * 32;
        #pragma unroll
        for (int i = 0; i < 4; i++){                  // A: 2048 granules (256 rows x 8)
            int g = tid + i * 512;
            int row = g >> 3, slot = g & 7;
            int pl = slot >> 2, gg = slot & 3;
            uint32_t d = SWZ((uint32_t)(row * 128 + pl * 64 + gg * 16));
            const __nv_bfloat16* src = (pl ? Alo : Ahi) + (size_t)(m0 + row) * KDIM + k0 + gg * 8;
            CP16(st + d, src);
        }
        #pragma unroll
        for (int i = 0; i < 2; i++){                  // B: 1024 granules (128 rows x 8)
            int g = tid + i * 512;
            int row = g >> 3, slot = g & 7;
            int pl = slot >> 2, gg = slot & 3;
            uint32_t d = SWZ((uint32_t)(32768u + row * 128 + pl * 64 + gg * 16));
            const __nv_bfloat16* src = (pl ? Blo : Bhi) + (size_t)(n0 + row) * KDIM + k0 + gg * 8;
            CP16(st + d, src);
        }
        asm volatile("cp.async.commit_group;" ::: "memory");
    };

    float acc[4][4][4];
    #pragma unroll
    for (int mi = 0; mi < 4; mi++)
        #pragma unroll
        for (int ni = 0; ni < 4; ni++)
            #pragma unroll
            for (int r = 0; r < 4; r++) acc[mi][ni][r] = 0.0f;

    load_tile(0);
    load_tile(1);

    const uint32_t aRow = (uint32_t)(lane & 15);
    const uint32_t aCol = (uint32_t)(lane >> 4) * 16u;
    const uint32_t bRow = (uint32_t)(((lane >> 4) & 1) * 8 + (lane & 7));
    const uint32_t bCol = (uint32_t)((lane >> 3) & 1) * 16u;

    #pragma unroll 1
    for (int t = 0; t < NCH; t++){
        if (t < NCH - 1) asm volatile("cp.async.wait_group 1;" ::: "memory");
        else             asm volatile("cp.async.wait_group 0;" ::: "memory");
        __syncthreads();

        const uint32_t sA = sbase + (uint32_t)(t % 3) * STG;
        const uint32_t sB = sA + 32768u;

        #pragma unroll
        for (int kk = 0; kk < 2; kk++){
            const uint32_t kb = (uint32_t)kk * 32u;
            uint32_t a[4][4], bh[8], bl[8];

            #pragma unroll
            for (int np = 0; np < 2; np++){           // B hi
                uint32_t ad = sB + SWZ((uint32_t)((wn + np*16 + bRow) * 128) + kb + bCol);
                asm volatile("ldmatrix.sync.aligned.m8n8.x4.shared.b16 {%0,%1,%2,%3},[%4];"
                    : "=r"(bh[np*4]), "=r"(bh[np*4+1]), "=r"(bh[np*4+2]), "=r"(bh[np*4+3]) : "r"(ad));
            }
            #pragma unroll
            for (int np = 0; np < 2; np++){           // B lo
                uint32_t ad = sB + SWZ((uint32_t)((wn + np*16 + bRow) * 128) + 64u + kb + bCol);
                asm volatile("ldmatrix.sync.aligned.m8n8.x4.shared.b16 {%0,%1,%2,%3},[%4];"
                    : "=r"(bl[np*4]), "=r"(bl[np*4+1]), "=r"(bl[np*4+2]), "=r"(bl[np*4+3]) : "r"(ad));
            }
            #pragma unroll
            for (int mi = 0; mi < 4; mi++){           // A hi
                uint32_t ad = sA + SWZ((uint32_t)((wm + mi*16 + aRow) * 128) + kb + aCol);
                asm volatile("ldmatrix.sync.aligned.m8n8.x4.shared.b16 {%0,%1,%2,%3},[%4];"
                    : "=r"(a[mi][0]), "=r"(a[mi][1]), "=r"(a[mi][2]), "=r"(a[mi][3]) : "r"(ad));
            }
            // P1: hi*hi  (16 independent accs)
            #pragma unroll
            for (int mi = 0; mi < 4; mi++)
                #pragma unroll
                for (int ni = 0; ni < 4; ni++)
                    mma16816(acc[mi][ni], a[mi], bh[(ni>>1)*4 + (ni&1)*2], bh[(ni>>1)*4 + (ni&1)*2 + 1]);
            // P3: hi*lo
            #pragma unroll
            for (int mi = 0; mi < 4; mi++)
                #pragma unroll
                for (int ni = 0; ni < 4; ni++)
                    mma16816(acc[mi][ni], a[mi], bl[(ni>>1)*4 + (ni&1)*2], bl[(ni>>1)*4 + (ni&1)*2 + 1]);
            #pragma unroll
            for (int mi = 0; mi < 4; mi++){           // A lo (reuse regs)
                uint32_t ad = sA + SWZ((uint32_t)((wm + mi*16 + aRow) * 128) + 64u + kb + aCol);
                asm volatile("ldmatrix.sync.aligned.m8n8.x4.shared.b16 {%0,%1,%2,%3},[%4];"
                    : "=r"(a[mi][0]), "=r"(a[mi][1]), "=r"(a[mi][2]), "=r"(a[mi][3]) : "r"(ad));
            }
            // P2: lo*hi
            #pragma unroll
            for (int mi = 0; mi < 4; mi++)
                #pragma unroll
                for (int ni = 0; ni < 4; ni++)
                    mma16816(acc[mi][ni], a[mi], bh[(ni>>1)*4 + (ni&1)*2], bh[(ni>>1)*4 + (ni&1)*2 + 1]);
        }
        if (t + 2 < NCH) load_tile(t + 2);
    }

    // ---------------- epilogue ----------------
    const int erow = lane >> 2;
    const int ecol = (lane & 3) * 2;
    #pragma unroll
    for (int mi = 0; mi < 4; mi++){
        #pragma unroll
        for (int ni = 0; ni < 4; ni++){
            const int row = m0 + wm + mi * 16 + erow;
            const int col = n0 + wn + ni * 8 + ecol;
            const float b0 = bias[col], b1 = bias[col + 1];
            float v0 = acc[mi][ni][0] + b0, v1 = acc[mi][ni][1] + b1;
            float v2 = acc[mi][ni][2] + b0, v3 = acc[mi][ni][3] + b1;
            if (EPI == 1){
                v0 = fmaxf(v0, 0.f); v1 = fmaxf(v1, 0.f);
                v2 = fmaxf(v2, 0.f); v3 = fmaxf(v3, 0.f);
            }
            if (EPI == 2){
                __nv_bfloat16 h0,h1,h2,h3,l0,l1,l2,l3;
                split_one(v0,h0,l0); split_one(v1,h1,l1);
                split_one(v2,h2,l2); split_one(v3,h3,l3);
                *(__nv_bfloat162*)(Chi + (size_t)row * N + col)       = __nv_bfloat162(h0, h1);
                *(__nv_bfloat162*)(Clo + (size_t)row * N + col)       = __nv_bfloat162(l0, l1);
                *(__nv_bfloat162*)(Chi + (size_t)(row + 8) * N + col) = __nv_bfloat162(h2, h3);
                *(__nv_bfloat162*)(Clo + (size_t)(row + 8) * N + col) = __nv_bfloat162(l2, l3);
            } else {
                *(float2*)(Cf + (size_t)row * N + col)       = make_float2(v0, v1);
                *(float2*)(Cf + (size_t)(row + 8) * N + col) = make_float2(v2, v3);
            }
        }
    }
}

// ---------------- attention over axis-0 (16) per (s,h) ---------------------
__global__ __launch_bounds__(128)
void attn_kernel(){
    const int s = blockIdx.x, h = blockIdx.y, tid = threadIdx.x;
    __shared__ float q[16][96], k[16][96], v[16][96], sc[16][17];

    const float* base = g_qkv + (size_t)s*2304 + h*DHEAD;
    for (int idx = tid; idx < 16*DHEAD; idx += 128){
        int l = idx / DHEAD, d = idx % DHEAD;
        size_t off = (size_t)l * ((size_t)SSEQ * 2304);
        q[l][d] = base[off + d];
        k[l][d] = base[off + 768 + d];
        v[l][d] = base[off + 1536 + d];
    }
    __syncthreads();

    const float scale = rsqrtf((float)DHEAD);
    for (int idx = tid; idx < 256; idx += 128){
        int l = idx >> 4, m = idx & 15;
        float acc = 0.f;
        #pragma unroll
        for (int d = 0; d < DHEAD; d++) acc = fmaf(q[l][d], k[m][d], acc);
        sc[l][m] = acc * scale;
    }
    __syncthreads();

    if (tid < 16){
        float mx = -INFINITY;
        #pragma unroll
        for (int m = 0; m < 16; m++) mx = fmaxf(mx, sc[tid][m]);
        float sum = 0.f;
        #pragma unroll
        for (int m = 0; m < 16; m++){ float e = expf(sc[tid][m]-mx); sc[tid][m]=e; sum+=e; }
        float inv = 1.f/sum;
        #pragma unroll
        for (int m = 0; m < 16; m++) sc[tid][m] *= inv;
    }
    __syncthreads();

    for (int idx = tid; idx < 16*DHEAD; idx += 128){
        int l = idx / DHEAD, d = idx % DHEAD;
        float acc = 0.f;
        #pragma unroll
        for (int m = 0; m < 16; m++) acc = fmaf(sc[l][m], v[m][d], acc);
        size_t o = ((size_t)l*SSEQ + s)*EMB + h*DHEAD + d;
        __nv_bfloat16 hh, ll;
        split_one(acc, hh, ll);
        g_chi[o] = hh;
        g_clo[o] = ll;
    }
}

// ---------------- prob + broadcast -----------------------------------------
__global__ __launch_bounds__(256)
void prob_bcast(const float* __restrict__ hbuf, const float* __restrict__ w2,
                const float* __restrict__ b2, float* __restrict__ out){
    const int r = blockIdx.x, tid = threadIdx.x;
    float p = 0.f;
    for (int j = tid; j < 384; j += 256)
        p = fmaf(hbuf[(size_t)r*384 + j], w2[j], p);
    __shared__ float red[256];
    red[tid] = p; __syncthreads();
    #pragma unroll
    for (int st = 128; st > 0; st >>= 1){
        if (tid < st) red[tid] += red[tid+st];
        __syncthreads();
    }
    __shared__ float probsh;
    if (tid == 0) probsh = red[0] + b2[0];
    __syncthreads();
    float4 pv4 = make_float4(probsh, probsh, probsh, probsh);
    float4* orow = (float4*)(out + (size_t)r*SSEQ);
    for (int c = tid; c < SSEQ/4; c += 256) orow[c] = pv4;
}

// ---------------------------------------------------------------------------
extern "C" void kernel_launch(void* const* d_in, const int* in_sizes, int n_in,
                              void* d_out, int out_size){
    const float* features = (const float*)d_in[0];
    const float* in_w  = (const float*)d_in[1];
    const float* in_b  = (const float*)d_in[2];
    const float* out_w = (const float*)d_in[3];
    const float* out_b = (const float*)d_in[4];
    const float* w1    = (const float*)d_in[5];
    const float* b1    = (const float*)d_in[6];
    const float* w2    = (const float*)d_in[7];
    const float* b2    = (const float*)d_in[8];
    float* out = (float*)d_out;

    float *qkv, *hb;
    __nv_bfloat16 *fhi,*flo,*chi,*clo,*ohi,*olo,*whi,*wlo;
    cudaGetSymbolAddress((void**)&qkv, g_qkv);
    cudaGetSymbolAddress((void**)&hb,  g_hbuf);
    cudaGetSymbolAddress((void**)&fhi, g_fhi);
    cudaGetSymbolAddress((void**)&flo, g_flo);
    cudaGetSymbolAddress((void**)&chi, g_chi);
    cudaGetSymbolAddress((void**)&clo, g_clo);
    cudaGetSymbolAddress((void**)&ohi, g_ohi);
    cudaGetSymbolAddress((void**)&olo, g_olo);
    cudaGetSymbolAddress((void**)&whi, g_whi);
    cudaGetSymbolAddress((void**)&wlo, g_wlo);

    const size_t OFF_OW = (size_t)2304*KDIM;
    const size_t OFF_W1 = (size_t)(2304+768)*KDIM;

    const int SMEM = 3 * 49152;   // 144 KB, 3-stage ring
    cudaFuncSetAttribute(gemm_mma<0>, cudaFuncAttributeMaxDynamicSharedMemorySize, SMEM);
    cudaFuncSetAttribute(gemm_mma<1>, cudaFuncAttributeMaxDynamicSharedMemorySize, SMEM);
    cudaFuncSetAttribute(gemm_mma<2>, cudaFuncAttributeMaxDynamicSharedMemorySize, SMEM);

    // launches 1-3: splits (gemm1 lands at slot 4 for the profiler)
    {
        size_t n4 = (size_t)MROWS*KDIM/4;
        split4<<<(unsigned)((n4+255)/256), 256>>>(features, fhi, flo, n4);
        n4 = (size_t)2304*KDIM/4;
        split4<<<(unsigned)((n4+255)/256), 256>>>(in_w, whi, wlo, n4);
        size_t na4 = (size_t)768*KDIM/4, nb4 = (size_t)384*KDIM/4;
        split4x2<<<(unsigned)((na4+nb4+255)/256), 256>>>(
            out_w, whi+OFF_OW, wlo+OFF_OW, na4,
            w1,    whi+OFF_W1, wlo+OFF_W1, nb4);
    }

    // 4) qkv = features @ in_w^T + in_b          (32768 x 2304)
    gemm_mma<0><<<dim3(2304/128, MROWS/256), 512, SMEM>>>(
        fhi, flo, whi, wlo, in_b, qkv, nullptr, nullptr, 2304);

    // 5) attention -> ctx hi/lo planes
    attn_kernel<<<dim3(SSEQ, NHEAD), 128>>>();

    // 6) att = ctx @ out_w^T + out_b -> hi/lo planes   (32768 x 768)
    gemm_mma<2><<<dim3(768/128, MROWS/256), 512, SMEM>>>(
        chi, clo, whi+OFF_OW, wlo+OFF_OW, out_b, nullptr, ohi, olo, 768);

    // 7) h = relu(att @ w1^T + b1)               (32768 x 384)
    gemm_mma<1><<<dim3(384/128, MROWS/256), 512, SMEM>>>(
        ohi, olo, whi+OFF_W1, wlo+OFF_W1, b1, hb, nullptr, nullptr, 384);

    // 8) prob + broadcast
    prob_bcast<<<MROWS, 256>>>(hb, w2, b2, out);
}

// round 6
// speedup vs baseline: 1.2876x; 1.2876x over previous
#include <cuda_runtime.h>
#include <cuda_bf16.h>
#include <math.h>
#include <stdint.h>

#define BBATCH 16
#define SSEQ   2048
#define EMB    768
#define NHEAD  8
#define DHEAD  96
#define MROWS  (BBATCH*SSEQ)   // 32768
#define KDIM   768
#define NCH    24              // 768 / BK, BK=32

// ---------------- scratch (device globals; allocation-free rule) -----------
__device__ float          g_qkv[(size_t)MROWS*2304];
__device__ __nv_bfloat16  g_fhi[(size_t)MROWS*KDIM];
__device__ __nv_bfloat16  g_flo[(size_t)MROWS*KDIM];
__device__ __nv_bfloat16  g_chi[(size_t)MROWS*KDIM];
__device__ __nv_bfloat16  g_clo[(size_t)MROWS*KDIM];
__device__ __nv_bfloat16  g_ohi[(size_t)MROWS*KDIM];
__device__ __nv_bfloat16  g_olo[(size_t)MROWS*KDIM];
__device__ float          g_hbuf[(size_t)MROWS*384];
__device__ float          g_prob[(size_t)MROWS];
__device__ __nv_bfloat16  g_whi[(size_t)(2304+768+384)*KDIM];
__device__ __nv_bfloat16  g_wlo[(size_t)(2304+768+384)*KDIM];

// ---------------- helpers ---------------------------------------------------
__device__ __forceinline__ uint32_t s2u(const void* p){
    uint32_t a;
    asm("{ .reg .u64 t; cvta.to.shared.u64 t, %1; cvt.u32.u64 %0, t; }":"=r"(a):"l"(p));
    return a;
}
#define SWZ(o) ((o) ^ (((o) >> 3) & 0x70))
#define CP16(s, g) asm volatile("cp.async.cg.shared.global [%0], [%1], 16;"::"r"(s),"l"(g):"memory")

__device__ __forceinline__ void mma16816(float* c, const uint32_t* a, uint32_t b0, uint32_t b1){
    asm volatile("mma.sync.aligned.m16n8k16.row.col.f32.bf16.bf16.f32 "
        "{%0,%1,%2,%3},{%4,%5,%6,%7},{%8,%9},{%0,%1,%2,%3};"
        : "+f"(c[0]), "+f"(c[1]), "+f"(c[2]), "+f"(c[3])
        : "r"(a[0]), "r"(a[1]), "r"(a[2]), "r"(a[3]), "r"(b0), "r"(b1));
}

__device__ __forceinline__ void split_one(float x, __nv_bfloat16& h, __nv_bfloat16& l){
    h = __float2bfloat16(x);
    l = __float2bfloat16(x - __bfloat162float(h));
}

// ---------------- fp32 -> bf16 hi/lo split (vectorized x4) -----------------
__global__ __launch_bounds__(256)
void split4(const float* __restrict__ src, __nv_bfloat16* __restrict__ hi,
            __nv_bfloat16* __restrict__ lo, size_t n4){
    size_t i = (size_t)blockIdx.x * blockDim.x + threadIdx.x;
    if (i >= n4) return;
    float4 v = ((const float4*)src)[i];
    __nv_bfloat16 h0,h1,h2,h3,l0,l1,l2,l3;
    split_one(v.x,h0,l0); split_one(v.y,h1,l1);
    split_one(v.z,h2,l2); split_one(v.w,h3,l3);
    ((__nv_bfloat162*)hi)[2*i]   = __nv_bfloat162(h0,h1);
    ((__nv_bfloat162*)hi)[2*i+1] = __nv_bfloat162(h2,h3);
    ((__nv_bfloat162*)lo)[2*i]   = __nv_bfloat162(l0,l1);
    ((__nv_bfloat162*)lo)[2*i+1] = __nv_bfloat162(l2,l3);
}

__global__ __launch_bounds__(256)
void split4x2(const float* __restrict__ sa, __nv_bfloat16* __restrict__ ha,
              __nv_bfloat16* __restrict__ la, size_t na4,
              const float* __restrict__ sb, __nv_bfloat16* __restrict__ hb,
              __nv_bfloat16* __restrict__ lb, size_t nb4){
    size_t i = (size_t)blockIdx.x * blockDim.x + threadIdx.x;
    const float* src; __nv_bfloat16 *hi, *lo;
    if (i < na4){ src = sa; hi = ha; lo = la; }
    else if (i < na4 + nb4){ i -= na4; src = sb; hi = hb; lo = lb; }
    else return;
    float4 v = ((const float4*)src)[i];
    __nv_bfloat16 h0,h1,h2,h3,l0,l1,l2,l3;
    split_one(v.x,h0,l0); split_one(v.y,h1,l1);
    split_one(v.z,h2,l2); split_one(v.w,h3,l3);
    ((__nv_bfloat162*)hi)[2*i]   = __nv_bfloat162(h0,h1);
    ((__nv_bfloat162*)hi)[2*i+1] = __nv_bfloat162(h2,h3);
    ((__nv_bfloat162*)lo)[2*i]   = __nv_bfloat162(l0,l1);
    ((__nv_bfloat162*)lo)[2*i+1] = __nv_bfloat162(l2,l3);
}

// ---------------- mma.sync GEMM (R4 config: 128x128, BK=32, 256thr, occ2) --
// 3-pass hi/lo split, shared loads: smem row = [hi 64B | lo 64B] (SW128).
// 3-stage cp.async ring (32KB/stage). 8 warps: 2m x 4n, warp tile 64x32.
// EPI: 0 fp32 out, 1 fp32+ReLU, 2 bf16 hi/lo planes out.
template<int EPI>
__global__ __launch_bounds__(256, 2)
void gemm_mma(const __nv_bfloat16* __restrict__ Ahi, const __nv_bfloat16* __restrict__ Alo,
              const __nv_bfloat16* __restrict__ Bhi, const __nv_bfloat16* __restrict__ Blo,
              const float* __restrict__ bias, float* __restrict__ Cf,
              __nv_bfloat16* __restrict__ Chi, __nv_bfloat16* __restrict__ Clo, int N)
{
    extern __shared__ __align__(1024) char sm[];
    const int tid = threadIdx.x, lane = tid & 31, warp = tid >> 5;
    const int m0 = blockIdx.y * 128, n0 = blockIdx.x * 128;
    const int wm = (warp & 1) * 64, wn = (warp >> 1) * 32;
    const uint32_t sbase = s2u(sm);

    auto load_tile = [&](int t){
        const uint32_t st = sbase + (uint32_t)(t % 3) * 32768u;
        const int k0 = t * 32;
        #pragma unroll
        for (int i = 0; i < 4; i++){                  // A granules
            int g = tid + i * 256;
            int row = g >> 3, slot = g & 7;
            int pl = slot >> 2, gg = slot & 3;
            uint32_t d = SWZ((uint32_t)(row * 128 + pl * 64 + gg * 16));
            const __nv_bfloat16* src = (pl ? Alo : Ahi) + (size_t)(m0 + row) * KDIM + k0 + gg * 8;
            CP16(st + d, src);
        }
        #pragma unroll
        for (int i = 0; i < 4; i++){                  // B granules
            int g = tid + i * 256;
            int row = g >> 3, slot = g & 7;
            int pl = slot >> 2, gg = slot & 3;
            uint32_t d = SWZ((uint32_t)(16384u + row * 128 + pl * 64 + gg * 16));
            const __nv_bfloat16* src = (pl ? Blo : Bhi) + (size_t)(n0 + row) * KDIM + k0 + gg * 8;
            CP16(st + d, src);
        }
        asm volatile("cp.async.commit_group;" ::: "memory");
    };

    float acc[4][4][4];
    #pragma unroll
    for (int mi = 0; mi < 4; mi++)
        #pragma unroll
        for (int ni = 0; ni < 4; ni++)
            #pragma unroll
            for (int r = 0; r < 4; r++) acc[mi][ni][r] = 0.0f;

    load_tile(0);
    load_tile(1);

    const uint32_t aRow = (uint32_t)(lane & 15);
    const uint32_t aCol = (uint32_t)(lane >> 4) * 16u;
    const uint32_t bRow = (uint32_t)(((lane >> 4) & 1) * 8 + (lane & 7));
    const uint32_t bCol = (uint32_t)((lane >> 3) & 1) * 16u;

    #pragma unroll 1
    for (int t = 0; t < NCH; t++){
        if (t < NCH - 1) asm volatile("cp.async.wait_group 1;" ::: "memory");
        else             asm volatile("cp.async.wait_group 0;" ::: "memory");
        __syncthreads();

        const uint32_t sA = sbase + (uint32_t)(t % 3) * 32768u;
        const uint32_t sB = sA + 16384u;

        #pragma unroll
        for (int kk = 0; kk < 2; kk++){
            const uint32_t kb = (uint32_t)kk * 32u;
            uint32_t a[4][4], bh[8], bl[8];

            #pragma unroll
            for (int np = 0; np < 2; np++){           // B hi
                uint32_t ad = sB + SWZ((uint32_t)((wn + np*16 + bRow) * 128) + kb + bCol);
                asm volatile("ldmatrix.sync.aligned.m8n8.x4.shared.b16 {%0,%1,%2,%3},[%4];"
                    : "=r"(bh[np*4]), "=r"(bh[np*4+1]), "=r"(bh[np*4+2]), "=r"(bh[np*4+3]) : "r"(ad));
            }
            #pragma unroll
            for (int np = 0; np < 2; np++){           // B lo
                uint32_t ad = sB + SWZ((uint32_t)((wn + np*16 + bRow) * 128) + 64u + kb + bCol);
                asm volatile("ldmatrix.sync.aligned.m8n8.x4.shared.b16 {%0,%1,%2,%3},[%4];"
                    : "=r"(bl[np*4]), "=r"(bl[np*4+1]), "=r"(bl[np*4+2]), "=r"(bl[np*4+3]) : "r"(ad));
            }
            #pragma unroll
            for (int mi = 0; mi < 4; mi++){           // A hi
                uint32_t ad = sA + SWZ((uint32_t)((wm + mi*16 + aRow) * 128) + kb + aCol);
                asm volatile("ldmatrix.sync.aligned.m8n8.x4.shared.b16 {%0,%1,%2,%3},[%4];"
                    : "=r"(a[mi][0]), "=r"(a[mi][1]), "=r"(a[mi][2]), "=r"(a[mi][3]) : "r"(ad));
            }
            // P1 (hi*hi) + P3 (hi*lo)
            #pragma unroll
            for (int mi = 0; mi < 4; mi++)
                #pragma unroll
                for (int ni = 0; ni < 4; ni++){
                    mma16816(acc[mi][ni], a[mi], bh[(ni>>1)*4 + (ni&1)*2], bh[(ni>>1)*4 + (ni&1)*2 + 1]);
                    mma16816(acc[mi][ni], a[mi], bl[(ni>>1)*4 + (ni&1)*2], bl[(ni>>1)*4 + (ni&1)*2 + 1]);
                }
            #pragma unroll
            for (int mi = 0; mi < 4; mi++){           // A lo (reuse regs)
                uint32_t ad = sA + SWZ((uint32_t)((wm + mi*16 + aRow) * 128) + 64u + kb + aCol);
                asm volatile("ldmatrix.sync.aligned.m8n8.x4.shared.b16 {%0,%1,%2,%3},[%4];"
                    : "=r"(a[mi][0]), "=r"(a[mi][1]), "=r"(a[mi][2]), "=r"(a[mi][3]) : "r"(ad));
            }
            // P2 (lo*hi)
            #pragma unroll
            for (int mi = 0; mi < 4; mi++)
                #pragma unroll
                for (int ni = 0; ni < 4; ni++)
                    mma16816(acc[mi][ni], a[mi], bh[(ni>>1)*4 + (ni&1)*2], bh[(ni>>1)*4 + (ni&1)*2 + 1]);
        }
        if (t + 2 < NCH) load_tile(t + 2);
    }

    const int erow = lane >> 2;
    const int ecol = (lane & 3) * 2;
    #pragma unroll
    for (int mi = 0; mi < 4; mi++){
        #pragma unroll
        for (int ni = 0; ni < 4; ni++){
            const int row = m0 + wm + mi * 16 + erow;
            const int col = n0 + wn + ni * 8 + ecol;
            const float b0 = bias[col], b1 = bias[col + 1];
            float v0 = acc[mi][ni][0] + b0, v1 = acc[mi][ni][1] + b1;
            float v2 = acc[mi][ni][2] + b0, v3 = acc[mi][ni][3] + b1;
            if (EPI == 1){
                v0 = fmaxf(v0, 0.f); v1 = fmaxf(v1, 0.f);
                v2 = fmaxf(v2, 0.f); v3 = fmaxf(v3, 0.f);
            }
            if (EPI == 2){
                __nv_bfloat16 h0,h1,h2,h3,l0,l1,l2,l3;
                split_one(v0,h0,l0); split_one(v1,h1,l1);
                split_one(v2,h2,l2); split_one(v3,h3,l3);
                *(__nv_bfloat162*)(Chi + (size_t)row * N + col)       = __nv_bfloat162(h0, h1);
                *(__nv_bfloat162*)(Clo + (size_t)row * N + col)       = __nv_bfloat162(l0, l1);
                *(__nv_bfloat162*)(Chi + (size_t)(row + 8) * N + col) = __nv_bfloat162(h2, h3);
                *(__nv_bfloat162*)(Clo + (size_t)(row + 8) * N + col) = __nv_bfloat162(l2, l3);
            } else {
                *(float2*)(Cf + (size_t)row * N + col)       = make_float2(v0, v1);
                *(float2*)(Cf + (size_t)(row + 8) * N + col) = make_float2(v2, v3);
            }
        }
    }
}

// ---------------- attention over axis-0 (16) per (s,h), vectorized ---------
__global__ __launch_bounds__(128)
void attn_kernel(){
    const int s = blockIdx.x, h = blockIdx.y, tid = threadIdx.x;
    // padded rows: 100 floats (400B) -> score-phase LDS conflict-free
    __shared__ float q[16][100], k[16][100], v[16][100];
    __shared__ float sc[16][17];

    const float* srcbase = g_qkv + (size_t)s*2304 + h*DHEAD;
    #pragma unroll
    for (int i = 0; i < 3; i++){                    // 384 float4 per tensor
        int g = tid + i * 128;
        int l = g / 24, c = g % 24;
        const float* p = srcbase + (size_t)l * ((size_t)SSEQ * 2304) + c * 4;
        *(float4*)&q[l][c*4] = *(const float4*)(p);
        *(float4*)&k[l][c*4] = *(const float4*)(p + 768);
        *(float4*)&v[l][c*4] = *(const float4*)(p + 1536);
    }
    __syncthreads();

    const float scale = rsqrtf((float)DHEAD);
    #pragma unroll
    for (int i = 0; i < 2; i++){                    // 256 scores
        int idx = tid + i * 128;
        int l = idx >> 4, m = idx & 15;
        float acc = 0.f;
        #pragma unroll
        for (int d = 0; d < DHEAD; d++) acc = fmaf(q[l][d], k[m][d], acc);
        sc[l][m] = acc * scale;
    }
    __syncthreads();

    if (tid < 16){
        float mx = -INFINITY;
        #pragma unroll
        for (int m = 0; m < 16; m++) mx = fmaxf(mx, sc[tid][m]);
        float sum = 0.f;
        #pragma unroll
        for (int m = 0; m < 16; m++){ float e = expf(sc[tid][m]-mx); sc[tid][m]=e; sum+=e; }
        float inv = 1.f/sum;
        #pragma unroll
        for (int m = 0; m < 16; m++) sc[tid][m] *= inv;
    }
    __syncthreads();

    // ctx: 16 x 96, pairs of d -> bf16x2 hi/lo stores (768 pairs, 6 iters)
    #pragma unroll
    for (int i = 0; i < 6; i++){
        int idx = tid + i * 128;
        int l = idx / 48, dp = idx % 48;
        int d = dp * 2;
        float a0 = 0.f, a1 = 0.f;
        #pragma unroll
        for (int m = 0; m < 16; m++){
            float w = sc[l][m];
            a0 = fmaf(w, v[m][d],   a0);
            a1 = fmaf(w, v[m][d+1], a1);
        }
        size_t o = ((size_t)l*SSEQ + s)*EMB + h*DHEAD + d;
        __nv_bfloat16 h0,h1,l0,l1;
        split_one(a0,h0,l0); split_one(a1,h1,l1);
        *(__nv_bfloat162*)(g_chi + o) = __nv_bfloat162(h0,h1);
        *(__nv_bfloat162*)(g_clo + o) = __nv_bfloat162(l0,l1);
    }
}

// ---------------- prob: one warp per row, shuffle reduction ----------------
__global__ __launch_bounds__(256)
void prob_compute(const float* __restrict__ hbuf, const float* __restrict__ w2,
                  const float* __restrict__ b2, float* __restrict__ probs){
    const int gw = (blockIdx.x * 256 + threadIdx.x) >> 5;   // global warp = row
    const int lane = threadIdx.x & 31;
    if (gw >= MROWS) return;
    const float4* row4 = (const float4*)(hbuf + (size_t)gw * 384);
    const float4* w4   = (const float4*)w2;
    float p = 0.f;
    #pragma unroll
    for (int j = 0; j < 3; j++){
        float4 a = row4[lane + j*32];
        float4 w = w4[lane + j*32];
        p = fmaf(a.x, w.x, p); p = fmaf(a.y, w.y, p);
        p = fmaf(a.z, w.z, p); p = fmaf(a.w, w.w, p);
    }
    #pragma unroll
    for (int o = 16; o > 0; o >>= 1) p += __shfl_xor_sync(0xFFFFFFFFu, p, o);
    if (lane == 0) probs[gw] = p + b2[0];
}

// ---------------- broadcast: out[r,:] = probs[r], streaming writes ---------
__global__ __launch_bounds__(256)
void bcast(const float* __restrict__ probs, float* __restrict__ out){
    const int r = blockIdx.x * 2 + (threadIdx.x >> 7);      // 2 rows per block
    const int t = threadIdx.x & 127;
    const float pv = probs[r];
    float4 p4 = make_float4(pv, pv, pv, pv);
    float4* orow = (float4*)(out + (size_t)r * SSEQ);
    #pragma unroll
    for (int i = 0; i < 4; i++) orow[t + i*128] = p4;
}

// ---------------------------------------------------------------------------
extern "C" void kernel_launch(void* const* d_in, const int* in_sizes, int n_in,
                              void* d_out, int out_size){
    const float* features = (const float*)d_in[0];
    const float* in_w  = (const float*)d_in[1];
    const float* in_b  = (const float*)d_in[2];
    const float* out_w = (const float*)d_in[3];
    const float* out_b = (const float*)d_in[4];
    const float* w1    = (const float*)d_in[5];
    const float* b1    = (const float*)d_in[6];
    const float* w2    = (const float*)d_in[7];
    const float* b2    = (const float*)d_in[8];
    float* out = (float*)d_out;

    float *qkv, *hb, *pb;
    __nv_bfloat16 *fhi,*flo,*chi,*clo,*ohi,*olo,*whi,*wlo;
    cudaGetSymbolAddress((void**)&qkv, g_qkv);
    cudaGetSymbolAddress((void**)&hb,  g_hbuf);
    cudaGetSymbolAddress((void**)&pb,  g_prob);
    cudaGetSymbolAddress((void**)&fhi, g_fhi);
    cudaGetSymbolAddress((void**)&flo, g_flo);
    cudaGetSymbolAddress((void**)&chi, g_chi);
    cudaGetSymbolAddress((void**)&clo, g_clo);
    cudaGetSymbolAddress((void**)&ohi, g_ohi);
    cudaGetSymbolAddress((void**)&olo, g_olo);
    cudaGetSymbolAddress((void**)&whi, g_whi);
    cudaGetSymbolAddress((void**)&wlo, g_wlo);

    const size_t OFF_OW = (size_t)2304*KDIM;
    const size_t OFF_W1 = (size_t)(2304+768)*KDIM;

    const int SMEM = 3 * 32768;   // 96 KB, 3-stage ring, 2 CTA/SM
    cudaFuncSetAttribute(gemm_mma<0>, cudaFuncAttributeMaxDynamicSharedMemorySize, SMEM);
    cudaFuncSetAttribute(gemm_mma<1>, cudaFuncAttributeMaxDynamicSharedMemorySize, SMEM);
    cudaFuncSetAttribute(gemm_mma<2>, cudaFuncAttributeMaxDynamicSharedMemorySize, SMEM);

    // launches 1-3: splits (keeps gemm1 in profiled slot)
    {
        size_t n4 = (size_t)MROWS*KDIM/4;
        split4<<<(unsigned)((n4+255)/256), 256>>>(features, fhi, flo, n4);
        n4 = (size_t)2304*KDIM/4;
        split4<<<(unsigned)((n4+255)/256), 256>>>(in_w, whi, wlo, n4);
        size_t na4 = (size_t)768*KDIM/4, nb4 = (size_t)384*KDIM/4;
        split4x2<<<(unsigned)((na4+nb4+255)/256), 256>>>(
            out_w, whi+OFF_OW, wlo+OFF_OW, na4,
            w1,    whi+OFF_W1, wlo+OFF_W1, nb4);
    }

    // 4) qkv = features @ in_w^T + in_b          (32768 x 2304)
    gemm_mma<0><<<dim3(2304/128, MROWS/128), 256, SMEM>>>(
        fhi, flo, whi, wlo, in_b, qkv, nullptr, nullptr, 2304);

    // 5) attention -> ctx hi/lo planes
    attn_kernel<<<dim3(SSEQ, NHEAD), 128>>>();

    // 6) att = ctx @ out_w^T + out_b -> hi/lo planes   (32768 x 768)
    gemm_mma<2><<<dim3(768/128, MROWS/128), 256, SMEM>>>(
        chi, clo, whi+OFF_OW, wlo+OFF_OW, out_b, nullptr, ohi, olo, 768);

    // 7) h = relu(att @ w1^T + b1)               (32768 x 384)
    gemm_mma<1><<<dim3(384/128, MROWS/128), 256, SMEM>>>(
        ohi, olo, whi+OFF_W1, wlo+OFF_W1, b1, hb, nullptr, nullptr, 384);

    // 8) prob per row, 9) broadcast
    prob_compute<<<MROWS/8, 256>>>(hb, w2, b2, pb);
    bcast<<<MROWS/2, 256>>>(pb, out);
}

// round 7
// speedup vs baseline: 1.7367x; 1.3488x over previous
#include <cuda_runtime.h>
#include <cuda_fp16.h>
#include <math.h>
#include <stdint.h>

#define BBATCH 16
#define SSEQ   2048
#define EMB    768
#define NHEAD  8
#define DHEAD  96
#define MROWS  (BBATCH*SSEQ)   // 32768
#define KDIM   768
#define NCH    24              // 768 / BK, BK=32

// ---------------- scratch (device globals; allocation-free rule) -----------
__device__ float   g_qkv[(size_t)MROWS*2304];
__device__ __half  g_fhi[(size_t)MROWS*KDIM];
__device__ __half  g_flo[(size_t)MROWS*KDIM];
__device__ __half  g_chi[(size_t)MROWS*KDIM];
__device__ __half  g_clo[(size_t)MROWS*KDIM];
__device__ __half  g_ohi[(size_t)MROWS*KDIM];
__device__ __half  g_olo[(size_t)MROWS*KDIM];
__device__ float   g_hbuf[(size_t)MROWS*384];
__device__ float   g_prob[(size_t)MROWS];
__device__ __half  g_whi[(size_t)(2304+768+384)*KDIM];
__device__ __half  g_wlo[(size_t)(2304+768+384)*KDIM];

// ---------------- helpers ---------------------------------------------------
__device__ __forceinline__ uint32_t s2u(const void* p){
    uint32_t a;
    asm("{ .reg .u64 t; cvta.to.shared.u64 t, %1; cvt.u32.u64 %0, t; }":"=r"(a):"l"(p));
    return a;
}
#define SWZ(o)   ((o) ^ (((o) >> 3) & 0x70))
#define SWZ64(o) ((o) ^ (((o) >> 3) & 0x30))
#define CP16(s, g) asm volatile("cp.async.cg.shared.global [%0], [%1], 16;"::"r"(s),"l"(g):"memory")

__device__ __forceinline__ void mma16816(float* c, const uint32_t* a, uint32_t b0, uint32_t b1){
    asm volatile("mma.sync.aligned.m16n8k16.row.col.f32.f16.f16.f32 "
        "{%0,%1,%2,%3},{%4,%5,%6,%7},{%8,%9},{%0,%1,%2,%3};"
        : "+f"(c[0]), "+f"(c[1]), "+f"(c[2]), "+f"(c[3])
        : "r"(a[0]), "r"(a[1]), "r"(a[2]), "r"(a[3]), "r"(b0), "r"(b1));
}

__device__ __forceinline__ void split_one(float x, __half& h, __half& l){
    h = __float2half(x);
    l = __float2half(x - __half2float(h));
}

// ---------------- fp32 -> fp16 hi/lo split (vectorized x4) -----------------
__global__ __launch_bounds__(256)
void split4(const float* __restrict__ src, __half* __restrict__ hi,
            __half* __restrict__ lo, size_t n4){
    size_t i = (size_t)blockIdx.x * blockDim.x + threadIdx.x;
    if (i >= n4) return;
    float4 v = ((const float4*)src)[i];
    __half h0,h1,h2,h3,l0,l1,l2,l3;
    split_one(v.x,h0,l0); split_one(v.y,h1,l1);
    split_one(v.z,h2,l2); split_one(v.w,h3,l3);
    ((__half2*)hi)[2*i]   = __halves2half2(h0,h1);
    ((__half2*)hi)[2*i+1] = __halves2half2(h2,h3);
    ((__half2*)lo)[2*i]   = __halves2half2(l0,l1);
    ((__half2*)lo)[2*i+1] = __halves2half2(l2,l3);
}

__global__ __launch_bounds__(256)
void split4x2(const float* __restrict__ sa, __half* __restrict__ ha,
              __half* __restrict__ la, size_t na4,
              const float* __restrict__ sb, __half* __restrict__ hb,
              __half* __restrict__ lb, size_t nb4){
    size_t i = (size_t)blockIdx.x * blockDim.x + threadIdx.x;
    const float* src; __half *hi, *lo;
    if (i < na4){ src = sa; hi = ha; lo = la; }
    else if (i < na4 + nb4){ i -= na4; src = sb; hi = hb; lo = lb; }
    else return;
    float4 v = ((const float4*)src)[i];
    __half h0,h1,h2,h3,l0,l1,l2,l3;
    split_one(v.x,h0,l0); split_one(v.y,h1,l1);
    split_one(v.z,h2,l2); split_one(v.w,h3,l3);
    ((__half2*)hi)[2*i]   = __halves2half2(h0,h1);
    ((__half2*)hi)[2*i+1] = __halves2half2(h2,h3);
    ((__half2*)lo)[2*i]   = __halves2half2(l0,l1);
    ((__half2*)lo)[2*i+1] = __halves2half2(l2,l3);
}

// ---------------- mma.sync GEMM, fp16 2-pass split --------------------------
// C = (Ahi + Alo) @ Bhi^T + bias  (Ah*Bl and Al*Bl dropped; fp16 rounding).
// CTA 128x128, BK=32, 256 thr, occ 2. Smem stage: A 128x[hi64|lo64] SW128
// (16KB) + B 128x64B hi-only SW64 (8KB) = 24KB; 3-stage cp.async ring.
// EPI: 0 fp32 out, 1 fp32+ReLU, 2 fp16 hi/lo planes out.
#define STG 24576u
template<int EPI>
__global__ __launch_bounds__(256, 2)
void gemm_mma(const __half* __restrict__ Ahi, const __half* __restrict__ Alo,
              const __half* __restrict__ Bhi,
              const float* __restrict__ bias, float* __restrict__ Cf,
              __half* __restrict__ Chi, __half* __restrict__ Clo, int N)
{
    extern __shared__ __align__(1024) char sm[];
    const int tid = threadIdx.x, lane = tid & 31, warp = tid >> 5;
    const int m0 = blockIdx.y * 128, n0 = blockIdx.x * 128;
    const int wm = (warp & 1) * 64, wn = (warp >> 1) * 32;
    const uint32_t sbase = s2u(sm);

    auto load_tile = [&](int t){
        const uint32_t st = sbase + (uint32_t)(t % 3) * STG;
        const int k0 = t * 32;
        #pragma unroll
        for (int i = 0; i < 4; i++){                  // A: 1024 granules
            int g = tid + i * 256;
            int row = g >> 3, slot = g & 7;
            int pl = slot >> 2, gg = slot & 3;
            uint32_t d = SWZ((uint32_t)(row * 128 + pl * 64 + gg * 16));
            const __half* src = (pl ? Alo : Ahi) + (size_t)(m0 + row) * KDIM + k0 + gg * 8;
            CP16(st + d, src);
        }
        #pragma unroll
        for (int i = 0; i < 2; i++){                  // B hi: 512 granules
            int g = tid + i * 256;
            int row = g >> 2, gg = g & 3;
            uint32_t d = SWZ64((uint32_t)(row * 64 + gg * 16));
            const __half* src = Bhi + (size_t)(n0 + row) * KDIM + k0 + gg * 8;
            CP16(st + 16384u + d, src);
        }
        asm volatile("cp.async.commit_group;" ::: "memory");
    };

    float acc[4][4][4];
    #pragma unroll
    for (int mi = 0; mi < 4; mi++)
        #pragma unroll
        for (int ni = 0; ni < 4; ni++)
            #pragma unroll
            for (int r = 0; r < 4; r++) acc[mi][ni][r] = 0.0f;

    load_tile(0);
    load_tile(1);

    const uint32_t aRow = (uint32_t)(lane & 15);
    const uint32_t aCol = (uint32_t)(lane >> 4) * 16u;
    const uint32_t bRow = (uint32_t)(((lane >> 4) & 1) * 8 + (lane & 7));
    const uint32_t bCol = (uint32_t)((lane >> 3) & 1) * 16u;

    #pragma unroll 1
    for (int t = 0; t < NCH; t++){
        if (t < NCH - 1) asm volatile("cp.async.wait_group 1;" ::: "memory");
        else             asm volatile("cp.async.wait_group 0;" ::: "memory");
        __syncthreads();

        const uint32_t sA = sbase + (uint32_t)(t % 3) * STG;
        const uint32_t sB = sA + 16384u;

        #pragma unroll
        for (int kk = 0; kk < 2; kk++){
            const uint32_t kb = (uint32_t)kk * 32u;
            uint32_t a[4][4], bh[8];

            #pragma unroll
            for (int np = 0; np < 2; np++){           // B hi (SW64 rows)
                uint32_t ad = sB + SWZ64((uint32_t)((wn + np*16 + bRow) * 64) + kb + bCol);
                asm volatile("ldmatrix.sync.aligned.m8n8.x4.shared.b16 {%0,%1,%2,%3},[%4];"
                    : "=r"(bh[np*4]), "=r"(bh[np*4+1]), "=r"(bh[np*4+2]), "=r"(bh[np*4+3]) : "r"(ad));
            }
            #pragma unroll
            for (int mi = 0; mi < 4; mi++){           // A hi
                uint32_t ad = sA + SWZ((uint32_t)((wm + mi*16 + aRow) * 128) + kb + aCol);
                asm volatile("ldmatrix.sync.aligned.m8n8.x4.shared.b16 {%0,%1,%2,%3},[%4];"
                    : "=r"(a[mi][0]), "=r"(a[mi][1]), "=r"(a[mi][2]), "=r"(a[mi][3]) : "r"(ad));
            }
            // P1: hi*hi
            #pragma unroll
            for (int mi = 0; mi < 4; mi++)
                #pragma unroll
                for (int ni = 0; ni < 4; ni++)
                    mma16816(acc[mi][ni], a[mi], bh[(ni>>1)*4 + (ni&1)*2], bh[(ni>>1)*4 + (ni&1)*2 + 1]);
            #pragma unroll
            for (int mi = 0; mi < 4; mi++){           // A lo (reuse regs)
                uint32_t ad = sA + SWZ((uint32_t)((wm + mi*16 + aRow) * 128) + 64u + kb + aCol);
                asm volatile("ldmatrix.sync.aligned.m8n8.x4.shared.b16 {%0,%1,%2,%3},[%4];"
                    : "=r"(a[mi][0]), "=r"(a[mi][1]), "=r"(a[mi][2]), "=r"(a[mi][3]) : "r"(ad));
            }
            // P2: lo*hi
            #pragma unroll
            for (int mi = 0; mi < 4; mi++)
                #pragma unroll
                for (int ni = 0; ni < 4; ni++)
                    mma16816(acc[mi][ni], a[mi], bh[(ni>>1)*4 + (ni&1)*2], bh[(ni>>1)*4 + (ni&1)*2 + 1]);
        }
        if (t + 2 < NCH) load_tile(t + 2);
    }

    const int erow = lane >> 2;
    const int ecol = (lane & 3) * 2;
    #pragma unroll
    for (int mi = 0; mi < 4; mi++){
        #pragma unroll
        for (int ni = 0; ni < 4; ni++){
            const int row = m0 + wm + mi * 16 + erow;
            const int col = n0 + wn + ni * 8 + ecol;
            const float b0 = bias[col], b1 = bias[col + 1];
            float v0 = acc[mi][ni][0] + b0, v1 = acc[mi][ni][1] + b1;
            float v2 = acc[mi][ni][2] + b0, v3 = acc[mi][ni][3] + b1;
            if (EPI == 1){
                v0 = fmaxf(v0, 0.f); v1 = fmaxf(v1, 0.f);
                v2 = fmaxf(v2, 0.f); v3 = fmaxf(v3, 0.f);
            }
            if (EPI == 2){
                __half h0,h1,h2,h3,l0,l1,l2,l3;
                split_one(v0,h0,l0); split_one(v1,h1,l1);
                split_one(v2,h2,l2); split_one(v3,h3,l3);
                *(__half2*)(Chi + (size_t)row * N + col)       = __halves2half2(h0, h1);
                *(__half2*)(Clo + (size_t)row * N + col)       = __halves2half2(l0, l1);
                *(__half2*)(Chi + (size_t)(row + 8) * N + col) = __halves2half2(h2, h3);
                *(__half2*)(Clo + (size_t)(row + 8) * N + col) = __halves2half2(l2, l3);
            } else {
                *(float2*)(Cf + (size_t)row * N + col)       = make_float2(v0, v1);
                *(float2*)(Cf + (size_t)(row + 8) * N + col) = make_float2(v2, v3);
            }
        }
    }
}

// ---------------- attention over axis-0 (16) per (s,h), vectorized ---------
__global__ __launch_bounds__(128)
void attn_kernel(){
    const int s = blockIdx.x, h = blockIdx.y, tid = threadIdx.x;
    __shared__ float q[16][100], k[16][100], v[16][100];
    __shared__ float sc[16][17];

    const float* srcbase = g_qkv + (size_t)s*2304 + h*DHEAD;
    #pragma unroll
    for (int i = 0; i < 3; i++){
        int g = tid + i * 128;
        int l = g / 24, c = g % 24;
        const float* p = srcbase + (size_t)l * ((size_t)SSEQ * 2304) + c * 4;
        *(float4*)&q[l][c*4] = *(const float4*)(p);
        *(float4*)&k[l][c*4] = *(const float4*)(p + 768);
        *(float4*)&v[l][c*4] = *(const float4*)(p + 1536);
    }
    __syncthreads();

    const float scale = rsqrtf((float)DHEAD);
    #pragma unroll
    for (int i = 0; i < 2; i++){
        int idx = tid + i * 128;
        int l = idx >> 4, m = idx & 15;
        float acc = 0.f;
        #pragma unroll
        for (int d = 0; d < DHEAD; d++) acc = fmaf(q[l][d], k[m][d], acc);
        sc[l][m] = acc * scale;
    }
    __syncthreads();

    if (tid < 16){
        float mx = -INFINITY;
        #pragma unroll
        for (int m = 0; m < 16; m++) mx = fmaxf(mx, sc[tid][m]);
        float sum = 0.f;
        #pragma unroll
        for (int m = 0; m < 16; m++){ float e = expf(sc[tid][m]-mx); sc[tid][m]=e; sum+=e; }
        float inv = 1.f/sum;
        #pragma unroll
        for (int m = 0; m < 16; m++) sc[tid][m] *= inv;
    }
    __syncthreads();

    #pragma unroll
    for (int i = 0; i < 6; i++){
        int idx = tid + i * 128;
        int l = idx / 48, dp = idx % 48;
        int d = dp * 2;
        float a0 = 0.f, a1 = 0.f;
        #pragma unroll
        for (int m = 0; m < 16; m++){
            float w = sc[l][m];
            a0 = fmaf(w, v[m][d],   a0);
            a1 = fmaf(w, v[m][d+1], a1);
        }
        size_t o = ((size_t)l*SSEQ + s)*EMB + h*DHEAD + d;
        __half h0,h1,l0,l1;
        split_one(a0,h0,l0); split_one(a1,h1,l1);
        *(__half2*)(g_chi + o) = __halves2half2(h0,h1);
        *(__half2*)(g_clo + o) = __halves2half2(l0,l1);
    }
}

// ---------------- prob: one warp per row, shuffle reduction ----------------
__global__ __launch_bounds__(256)
void prob_compute(const float* __restrict__ hbuf, const float* __restrict__ w2,
                  const float* __restrict__ b2, float* __restrict__ probs){
    const int gw = (blockIdx.x * 256 + threadIdx.x) >> 5;
    const int lane = threadIdx.x & 31;
    if (gw >= MROWS) return;
    const float4* row4 = (const float4*)(hbuf + (size_t)gw * 384);
    const float4* w4   = (const float4*)w2;
    float p = 0.f;
    #pragma unroll
    for (int j = 0; j < 3; j++){
        float4 a = row4[lane + j*32];
        float4 w = w4[lane + j*32];
        p = fmaf(a.x, w.x, p); p = fmaf(a.y, w.y, p);
        p = fmaf(a.z, w.z, p); p = fmaf(a.w, w.w, p);
    }
    #pragma unroll
    for (int o = 16; o > 0; o >>= 1) p += __shfl_xor_sync(0xFFFFFFFFu, p, o);
    if (lane == 0) probs[gw] = p + b2[0];
}

// ---------------- broadcast: out[r,:] = probs[r] ----------------------------
__global__ __launch_bounds__(256)
void bcast(const float* __restrict__ probs, float* __restrict__ out){
    const int r = blockIdx.x * 2 + (threadIdx.x >> 7);
    const int t = threadIdx.x & 127;
    const float pv = probs[r];
    float4 p4 = make_float4(pv, pv, pv, pv);
    float4* orow = (float4*)(out + (size_t)r * SSEQ);
    #pragma unroll
    for (int i = 0; i < 4; i++) orow[t + i*128] = p4;
}

// ---------------------------------------------------------------------------
extern "C" void kernel_launch(void* const* d_in, const int* in_sizes, int n_in,
                              void* d_out, int out_size){
    const float* features = (const float*)d_in[0];
    const float* in_w  = (const float*)d_in[1];
    const float* in_b  = (const float*)d_in[2];
    const float* out_w = (const float*)d_in[3];
    const float* out_b = (const float*)d_in[4];
    const float* w1    = (const float*)d_in[5];
    const float* b1    = (const float*)d_in[6];
    const float* w2    = (const float*)d_in[7];
    const float* b2    = (const float*)d_in[8];
    float* out = (float*)d_out;

    float *qkv, *hb, *pb;
    __half *fhi,*flo,*chi,*clo,*ohi,*olo,*whi,*wlo;
    cudaGetSymbolAddress((void**)&qkv, g_qkv);
    cudaGetSymbolAddress((void**)&hb,  g_hbuf);
    cudaGetSymbolAddress((void**)&pb,  g_prob);
    cudaGetSymbolAddress((void**)&fhi, g_fhi);
    cudaGetSymbolAddress((void**)&flo, g_flo);
    cudaGetSymbolAddress((void**)&chi, g_chi);
    cudaGetSymbolAddress((void**)&clo, g_clo);
    cudaGetSymbolAddress((void**)&ohi, g_ohi);
    cudaGetSymbolAddress((void**)&olo, g_olo);
    cudaGetSymbolAddress((void**)&whi, g_whi);
    cudaGetSymbolAddress((void**)&wlo, g_wlo);

    const size_t OFF_OW = (size_t)2304*KDIM;
    const size_t OFF_W1 = (size_t)(2304+768)*KDIM;

    const int SMEM = 3 * 24576;   // 72 KB, 3-stage ring, 2 CTA/SM
    cudaFuncSetAttribute(gemm_mma<0>, cudaFuncAttributeMaxDynamicSharedMemorySize, SMEM);
    cudaFuncSetAttribute(gemm_mma<1>, cudaFuncAttributeMaxDynamicSharedMemorySize, SMEM);
    cudaFuncSetAttribute(gemm_mma<2>, cudaFuncAttributeMaxDynamicSharedMemorySize, SMEM);

    // launches 1-3: splits (keeps gemm1 in profiled slot)
    {
        size_t n4 = (size_t)MROWS*KDIM/4;
        split4<<<(unsigned)((n4+255)/256), 256>>>(features, fhi, flo, n4);
        n4 = (size_t)2304*KDIM/4;
        split4<<<(unsigned)((n4+255)/256), 256>>>(in_w, whi, wlo, n4);
        size_t na4 = (size_t)768*KDIM/4, nb4 = (size_t)384*KDIM/4;
        split4x2<<<(unsigned)((na4+nb4+255)/256), 256>>>(
            out_w, whi+OFF_OW, wlo+OFF_OW, na4,
            w1,    whi+OFF_W1, wlo+OFF_W1, nb4);
    }

    // 4) qkv = features @ in_w^T + in_b          (32768 x 2304)
    gemm_mma<0><<<dim3(2304/128, MROWS/128), 256, SMEM>>>(
        fhi, flo, whi, in_b, qkv, nullptr, nullptr, 2304);

    // 5) attention -> ctx hi/lo planes
    attn_kernel<<<dim3(SSEQ, NHEAD), 128>>>();

    // 6) att = ctx @ out_w^T + out_b -> hi/lo planes   (32768 x 768)
    gemm_mma<2><<<dim3(768/128, MROWS/128), 256, SMEM>>>(
        chi, clo, whi+OFF_OW, out_b, nullptr, ohi, olo, 768);

    // 7) h = relu(att @ w1^T + b1)               (32768 x 384)
    gemm_mma<1><<<dim3(384/128, MROWS/128), 256, SMEM>>>(
        ohi, olo, whi+OFF_W1, b1, hb, nullptr, nullptr, 384);

    // 8) prob per row, 9) broadcast
    prob_compute<<<MROWS/8, 256>>>(hb, w2, b2, pb);
    bcast<<<MROWS/2, 256>>>(pb, out);
}

// round 8
// speedup vs baseline: 1.8753x; 1.0798x over previous
#include <cuda_runtime.h>
#include <cuda_fp16.h>
#include <math.h>
#include <stdint.h>

#define BBATCH 16
#define SSEQ   2048
#define EMB    768
#define NHEAD  8
#define DHEAD  96
#define MROWS  (BBATCH*SSEQ)   // 32768
#define KDIM   768
#define NCH    24              // 768 / BK, BK=32

// ---------------- scratch (device globals; allocation-free rule) -----------
__device__ float   g_qkv[(size_t)MROWS*2304];
__device__ __half  g_fhi[(size_t)MROWS*KDIM];
__device__ __half  g_flo[(size_t)MROWS*KDIM];
__device__ __half  g_chi[(size_t)MROWS*KDIM];
__device__ __half  g_clo[(size_t)MROWS*KDIM];
__device__ __half  g_ohi[(size_t)MROWS*KDIM];
__device__ __half  g_olo[(size_t)MROWS*KDIM];
__device__ float   g_hbuf[(size_t)MROWS*384];
__device__ float   g_prob[(size_t)MROWS];
__device__ __half  g_whi[(size_t)(2304+768+384)*KDIM];
__device__ __half  g_wlo[(size_t)(2304+768+384)*KDIM];

// ---------------- helpers ---------------------------------------------------
__device__ __forceinline__ uint32_t s2u(const void* p){
    uint32_t a;
    asm("{ .reg .u64 t; cvta.to.shared.u64 t, %1; cvt.u32.u64 %0, t; }":"=r"(a):"l"(p));
    return a;
}
#define SWZ(o)   ((o) ^ (((o) >> 3) & 0x70))
#define SWZ64(o) ((o) ^ (((o) >> 3) & 0x30))
#define CP16(s, g) asm volatile("cp.async.cg.shared.global [%0], [%1], 16;"::"r"(s),"l"(g):"memory")

__device__ __forceinline__ void mma16816(float* c, const uint32_t* a, uint32_t b0, uint32_t b1){
    asm volatile("mma.sync.aligned.m16n8k16.row.col.f32.f16.f16.f32 "
        "{%0,%1,%2,%3},{%4,%5,%6,%7},{%8,%9},{%0,%1,%2,%3};"
        : "+f"(c[0]), "+f"(c[1]), "+f"(c[2]), "+f"(c[3])
        : "r"(a[0]), "r"(a[1]), "r"(a[2]), "r"(a[3]), "r"(b0), "r"(b1));
}

__device__ __forceinline__ void split_one(float x, __half& h, __half& l){
    h = __float2half(x);
    l = __float2half(x - __half2float(h));
}

// ---------------- fp32 -> fp16 hi/lo split (vectorized x4) -----------------
__global__ __launch_bounds__(256)
void split4(const float* __restrict__ src, __half* __restrict__ hi,
            __half* __restrict__ lo, size_t n4){
    size_t i = (size_t)blockIdx.x * blockDim.x + threadIdx.x;
    if (i >= n4) return;
    float4 v = ((const float4*)src)[i];
    __half h0,h1,h2,h3,l0,l1,l2,l3;
    split_one(v.x,h0,l0); split_one(v.y,h1,l1);
    split_one(v.z,h2,l2); split_one(v.w,h3,l3);
    ((__half2*)hi)[2*i]   = __halves2half2(h0,h1);
    ((__half2*)hi)[2*i+1] = __halves2half2(h2,h3);
    ((__half2*)lo)[2*i]   = __halves2half2(l0,l1);
    ((__half2*)lo)[2*i+1] = __halves2half2(l2,l3);
}

__global__ __launch_bounds__(256)
void split4x2(const float* __restrict__ sa, __half* __restrict__ ha,
              __half* __restrict__ la, size_t na4,
              const float* __restrict__ sb, __half* __restrict__ hb,
              __half* __restrict__ lb, size_t nb4){
    size_t i = (size_t)blockIdx.x * blockDim.x + threadIdx.x;
    const float* src; __half *hi, *lo;
    if (i < na4){ src = sa; hi = ha; lo = la; }
    else if (i < na4 + nb4){ i -= na4; src = sb; hi = hb; lo = lb; }
    else return;
    float4 v = ((const float4*)src)[i];
    __half h0,h1,h2,h3,l0,l1,l2,l3;
    split_one(v.x,h0,l0); split_one(v.y,h1,l1);
    split_one(v.z,h2,l2); split_one(v.w,h3,l3);
    ((__half2*)hi)[2*i]   = __halves2half2(h0,h1);
    ((__half2*)hi)[2*i+1] = __halves2half2(h2,h3);
    ((__half2*)lo)[2*i]   = __halves2half2(l0,l1);
    ((__half2*)lo)[2*i+1] = __halves2half2(l2,l3);
}

// ---------------- mma.sync GEMM, fp16 split, PASSES = 1 or 2 ----------------
// PASSES=2: C = (Ahi + Alo) @ Bhi^T + bias.  PASSES=1: C = Ahi @ Bhi^T + bias.
// CTA 128x128, BK=32, 256 thr, occ 2, 3-stage cp.async ring; loads issued
// BEFORE compute each iteration. EPI: 0 fp32, 1 fp32+ReLU, 2 fp16 hi/lo out.
template<int EPI, int PASSES>
__global__ __launch_bounds__(256, 2)
void gemm_mma(const __half* __restrict__ Ahi, const __half* __restrict__ Alo,
              const __half* __restrict__ Bhi,
              const float* __restrict__ bias, float* __restrict__ Cf,
              __half* __restrict__ Chi, __half* __restrict__ Clo, int N)
{
    extern __shared__ __align__(1024) char sm[];
    constexpr uint32_t AROW = (PASSES == 2) ? 128u : 64u;  // A smem row bytes
    constexpr uint32_t BOFF = 128u * AROW;                 // B region offset
    constexpr uint32_t STGB = BOFF + 8192u;                // stage bytes
    const int tid = threadIdx.x, lane = tid & 31, warp = tid >> 5;
    const int m0 = blockIdx.y * 128, n0 = blockIdx.x * 128;
    const int wm = (warp & 1) * 64, wn = (warp >> 1) * 32;
    const uint32_t sbase = s2u(sm);

    auto load_tile = [&](int t){
        const uint32_t st = sbase + (uint32_t)(t % 3) * STGB;
        const int k0 = t * 32;
        if (PASSES == 2){
            #pragma unroll
            for (int i = 0; i < 4; i++){              // A hi+lo: 1024 granules
                int g = tid + i * 256;
                int row = g >> 3, slot = g & 7;
                int pl = slot >> 2, gg = slot & 3;
                uint32_t d = SWZ((uint32_t)(row * 128 + pl * 64 + gg * 16));
                const __half* src = (pl ? Alo : Ahi) + (size_t)(m0 + row) * KDIM + k0 + gg * 8;
                CP16(st + d, src);
            }
        } else {
            #pragma unroll
            for (int i = 0; i < 2; i++){              // A hi only: 512 granules
                int g = tid + i * 256;
                int row = g >> 2, gg = g & 3;
                uint32_t d = SWZ64((uint32_t)(row * 64 + gg * 16));
                const __half* src = Ahi + (size_t)(m0 + row) * KDIM + k0 + gg * 8;
                CP16(st + d, src);
            }
        }
        #pragma unroll
        for (int i = 0; i < 2; i++){                  // B hi: 512 granules
            int g = tid + i * 256;
            int row = g >> 2, gg = g & 3;
            uint32_t d = SWZ64((uint32_t)(row * 64 + gg * 16));
            const __half* src = Bhi + (size_t)(n0 + row) * KDIM + k0 + gg * 8;
            CP16(st + BOFF + d, src);
        }
        asm volatile("cp.async.commit_group;" ::: "memory");
    };

    float acc[4][4][4];
    #pragma unroll
    for (int mi = 0; mi < 4; mi++)
        #pragma unroll
        for (int ni = 0; ni < 4; ni++)
            #pragma unroll
            for (int r = 0; r < 4; r++) acc[mi][ni][r] = 0.0f;

    load_tile(0);
    load_tile(1);

    const uint32_t aRow = (uint32_t)(lane & 15);
    const uint32_t aCol = (uint32_t)(lane >> 4) * 16u;
    const uint32_t bRow = (uint32_t)(((lane >> 4) & 1) * 8 + (lane & 7));
    const uint32_t bCol = (uint32_t)((lane >> 3) & 1) * 16u;

    #pragma unroll 1
    for (int t = 0; t < NCH; t++){
        if (t < NCH - 1) asm volatile("cp.async.wait_group 1;" ::: "memory");
        else             asm volatile("cp.async.wait_group 0;" ::: "memory");
        __syncthreads();
        if (t + 2 < NCH) load_tile(t + 2);            // overlap loads with MMA

        const uint32_t sA = sbase + (uint32_t)(t % 3) * STGB;
        const uint32_t sB = sA + BOFF;

        #pragma unroll
        for (int kk = 0; kk < 2; kk++){
            const uint32_t kb = (uint32_t)kk * 32u;
            uint32_t a[4][4], bh[8];

            #pragma unroll
            for (int np = 0; np < 2; np++){           // B hi (SW64 rows)
                uint32_t ad = sB + SWZ64((uint32_t)((wn + np*16 + bRow) * 64) + kb + bCol);
                asm volatile("ldmatrix.sync.aligned.m8n8.x4.shared.b16 {%0,%1,%2,%3},[%4];"
                    : "=r"(bh[np*4]), "=r"(bh[np*4+1]), "=r"(bh[np*4+2]), "=r"(bh[np*4+3]) : "r"(ad));
            }
            #pragma unroll
            for (int mi = 0; mi < 4; mi++){           // A hi
                uint32_t ad;
                if (PASSES == 2) ad = sA + SWZ((uint32_t)((wm + mi*16 + aRow) * 128) + kb + aCol);
                else             ad = sA + SWZ64((uint32_t)((wm + mi*16 + aRow) * 64) + kb + aCol);
                asm volatile("ldmatrix.sync.aligned.m8n8.x4.shared.b16 {%0,%1,%2,%3},[%4];"
                    : "=r"(a[mi][0]), "=r"(a[mi][1]), "=r"(a[mi][2]), "=r"(a[mi][3]) : "r"(ad));
            }
            #pragma unroll
            for (int mi = 0; mi < 4; mi++)            // P1: hi*hi
                #pragma unroll
                for (int ni = 0; ni < 4; ni++)
                    mma16816(acc[mi][ni], a[mi], bh[(ni>>1)*4 + (ni&1)*2], bh[(ni>>1)*4 + (ni&1)*2 + 1]);
            if (PASSES == 2){
                #pragma unroll
                for (int mi = 0; mi < 4; mi++){       // A lo (reuse regs)
                    uint32_t ad = sA + SWZ((uint32_t)((wm + mi*16 + aRow) * 128) + 64u + kb + aCol);
                    asm volatile("ldmatrix.sync.aligned.m8n8.x4.shared.b16 {%0,%1,%2,%3},[%4];"
                        : "=r"(a[mi][0]), "=r"(a[mi][1]), "=r"(a[mi][2]), "=r"(a[mi][3]) : "r"(ad));
                }
                #pragma unroll
                for (int mi = 0; mi < 4; mi++)        // P2: lo*hi
                    #pragma unroll
                    for (int ni = 0; ni < 4; ni++)
                        mma16816(acc[mi][ni], a[mi], bh[(ni>>1)*4 + (ni&1)*2], bh[(ni>>1)*4 + (ni&1)*2 + 1]);
            }
        }
    }

    const int erow = lane >> 2;
    const int ecol = (lane & 3) * 2;
    #pragma unroll
    for (int mi = 0; mi < 4; mi++){
        #pragma unroll
        for (int ni = 0; ni < 4; ni++){
            const int row = m0 + wm + mi * 16 + erow;
            const int col = n0 + wn + ni * 8 + ecol;
            const float b0 = bias[col], b1 = bias[col + 1];
            float v0 = acc[mi][ni][0] + b0, v1 = acc[mi][ni][1] + b1;
            float v2 = acc[mi][ni][2] + b0, v3 = acc[mi][ni][3] + b1;
            if (EPI == 1){
                v0 = fmaxf(v0, 0.f); v1 = fmaxf(v1, 0.f);
                v2 = fmaxf(v2, 0.f); v3 = fmaxf(v3, 0.f);
            }
            if (EPI == 2){
                __half h0,h1,h2,h3,l0,l1,l2,l3;
                split_one(v0,h0,l0); split_one(v1,h1,l1);
                split_one(v2,h2,l2); split_one(v3,h3,l3);
                *(__half2*)(Chi + (size_t)row * N + col)       = __halves2half2(h0, h1);
                *(__half2*)(Clo + (size_t)row * N + col)       = __halves2half2(l0, l1);
                *(__half2*)(Chi + (size_t)(row + 8) * N + col) = __halves2half2(h2, h3);
                *(__half2*)(Clo + (size_t)(row + 8) * N + col) = __halves2half2(l2, l3);
            } else {
                *(float2*)(Cf + (size_t)row * N + col)       = make_float2(v0, v1);
                *(float2*)(Cf + (size_t)(row + 8) * N + col) = make_float2(v2, v3);
            }
        }
    }
}

// ---------------- attention over axis-0 (16) per (s,h), vectorized ---------
__global__ __launch_bounds__(128)
void attn_kernel(){
    const int s = blockIdx.x, h = blockIdx.y, tid = threadIdx.x;
    __shared__ float q[16][100], k[16][100], v[16][100];
    __shared__ float sc[16][17];

    const float* srcbase = g_qkv + (size_t)s*2304 + h*DHEAD;
    #pragma unroll
    for (int i = 0; i < 3; i++){
        int g = tid + i * 128;
        int l = g / 24, c = g % 24;
        const float* p = srcbase + (size_t)l * ((size_t)SSEQ * 2304) + c * 4;
        *(float4*)&q[l][c*4] = *(const float4*)(p);
        *(float4*)&k[l][c*4] = *(const float4*)(p + 768);
        *(float4*)&v[l][c*4] = *(const float4*)(p + 1536);
    }
    __syncthreads();

    const float scale = rsqrtf((float)DHEAD);
    #pragma unroll
    for (int i = 0; i < 2; i++){
        int idx = tid + i * 128;
        int l = idx >> 4, m = idx & 15;
        float acc = 0.f;
        #pragma unroll
        for (int d = 0; d < DHEAD; d++) acc = fmaf(q[l][d], k[m][d], acc);
        sc[l][m] = acc * scale;
    }
    __syncthreads();

    if (tid < 16){
        float mx = -INFINITY;
        #pragma unroll
        for (int m = 0; m < 16; m++) mx = fmaxf(mx, sc[tid][m]);
        float sum = 0.f;
        #pragma unroll
        for (int m = 0; m < 16; m++){ float e = expf(sc[tid][m]-mx); sc[tid][m]=e; sum+=e; }
        float inv = 1.f/sum;
        #pragma unroll
        for (int m = 0; m < 16; m++) sc[tid][m] *= inv;
    }
    __syncthreads();

    #pragma unroll
    for (int i = 0; i < 6; i++){
        int idx = tid + i * 128;
        int l = idx / 48, dp = idx % 48;
        int d = dp * 2;
        float a0 = 0.f, a1 = 0.f;
        #pragma unroll
        for (int m = 0; m < 16; m++){
            float w = sc[l][m];
            a0 = fmaf(w, v[m][d],   a0);
            a1 = fmaf(w, v[m][d+1], a1);
        }
        size_t o = ((size_t)l*SSEQ + s)*EMB + h*DHEAD + d;
        __half h0,h1,l0,l1;
        split_one(a0,h0,l0); split_one(a1,h1,l1);
        *(__half2*)(g_chi + o) = __halves2half2(h0,h1);
        *(__half2*)(g_clo + o) = __halves2half2(l0,l1);
    }
}

// ---------------- prob: one warp per row, shuffle reduction ----------------
__global__ __launch_bounds__(256)
void prob_compute(const float* __restrict__ hbuf, const float* __restrict__ w2,
                  const float* __restrict__ b2, float* __restrict__ probs){
    const int gw = (blockIdx.x * 256 + threadIdx.x) >> 5;
    const int lane = threadIdx.x & 31;
    if (gw >= MROWS) return;
    const float4* row4 = (const float4*)(hbuf + (size_t)gw * 384);
    const float4* w4   = (const float4*)w2;
    float p = 0.f;
    #pragma unroll
    for (int j = 0; j < 3; j++){
        float4 a = row4[lane + j*32];
        float4 w = w4[lane + j*32];
        p = fmaf(a.x, w.x, p); p = fmaf(a.y, w.y, p);
        p = fmaf(a.z, w.z, p); p = fmaf(a.w, w.w, p);
    }
    #pragma unroll
    for (int o = 16; o > 0; o >>= 1) p += __shfl_xor_sync(0xFFFFFFFFu, p, o);
    if (lane == 0) probs[gw] = p + b2[0];
}

// ---------------- broadcast: out[r,:] = probs[r] ----------------------------
__global__ __launch_bounds__(256)
void bcast(const float* __restrict__ probs, float* __restrict__ out){
    const int r = blockIdx.x * 2 + (threadIdx.x >> 7);
    const int t = threadIdx.x & 127;
    const float pv = probs[r];
    float4 p4 = make_float4(pv, pv, pv, pv);
    float4* orow = (float4*)(out + (size_t)r * SSEQ);
    #pragma unroll
    for (int i = 0; i < 4; i++) orow[t + i*128] = p4;
}

// ---------------------------------------------------------------------------
extern "C" void kernel_launch(void* const* d_in, const int* in_sizes, int n_in,
                              void* d_out, int out_size){
    const float* features = (const float*)d_in[0];
    const float* in_w  = (const float*)d_in[1];
    const float* in_b  = (const float*)d_in[2];
    const float* out_w = (const float*)d_in[3];
    const float* out_b = (const float*)d_in[4];
    const float* w1    = (const float*)d_in[5];
    const float* b1    = (const float*)d_in[6];
    const float* w2    = (const float*)d_in[7];
    const float* b2    = (const float*)d_in[8];
    float* out = (float*)d_out;

    float *qkv, *hb, *pb;
    __half *fhi,*flo,*chi,*clo,*ohi,*olo,*whi,*wlo;
    cudaGetSymbolAddress((void**)&qkv, g_qkv);
    cudaGetSymbolAddress((void**)&hb,  g_hbuf);
    cudaGetSymbolAddress((void**)&pb,  g_prob);
    cudaGetSymbolAddress((void**)&fhi, g_fhi);
    cudaGetSymbolAddress((void**)&flo, g_flo);
    cudaGetSymbolAddress((void**)&chi, g_chi);
    cudaGetSymbolAddress((void**)&clo, g_clo);
    cudaGetSymbolAddress((void**)&ohi, g_ohi);
    cudaGetSymbolAddress((void**)&olo, g_olo);
    cudaGetSymbolAddress((void**)&whi, g_whi);
    cudaGetSymbolAddress((void**)&wlo, g_wlo);

    const size_t OFF_V  = (size_t)1536*KDIM;
    const size_t OFF_OW = (size_t)2304*KDIM;
    const size_t OFF_W1 = (size_t)(2304+768)*KDIM;

    const int SMEM2 = 3 * 24576;   // PASSES=2 stage ring
    const int SMEM1 = 3 * 16384;   // PASSES=1 stage ring
    cudaFuncSetAttribute(gemm_mma<0,1>, cudaFuncAttributeMaxDynamicSharedMemorySize, SMEM1);
    cudaFuncSetAttribute(gemm_mma<0,2>, cudaFuncAttributeMaxDynamicSharedMemorySize, SMEM2);
    cudaFuncSetAttribute(gemm_mma<1,2>, cudaFuncAttributeMaxDynamicSharedMemorySize, SMEM2);
    cudaFuncSetAttribute(gemm_mma<2,2>, cudaFuncAttributeMaxDynamicSharedMemorySize, SMEM2);

    // launches 1-3: splits (keeps QK gemm in profiled slot #4)
    {
        size_t n4 = (size_t)MROWS*KDIM/4;
        split4<<<(unsigned)((n4+255)/256), 256>>>(features, fhi, flo, n4);
        n4 = (size_t)2304*KDIM/4;
        split4<<<(unsigned)((n4+255)/256), 256>>>(in_w, whi, wlo, n4);
        size_t na4 = (size_t)768*KDIM/4, nb4 = (size_t)384*KDIM/4;
        split4x2<<<(unsigned)((na4+nb4+255)/256), 256>>>(
            out_w, whi+OFF_OW, wlo+OFF_OW, na4,
            w1,    whi+OFF_W1, wlo+OFF_W1, nb4);
    }

    // 4) QK = features @ in_w[0:1536]^T + b  (1-pass: softmax damps the error)
    gemm_mma<0,1><<<dim3(1536/128, MROWS/128), 256, SMEM1>>>(
        fhi, nullptr, whi, in_b, qkv, nullptr, nullptr, 2304);

    // 5) V  = features @ in_w[1536:2304]^T + b  (2-pass: enters ctx linearly)
    gemm_mma<0,2><<<dim3(768/128, MROWS/128), 256, SMEM2>>>(
        fhi, flo, whi + OFF_V, in_b + 1536, qkv + 1536, nullptr, nullptr, 2304);

    // 6) attention -> ctx hi/lo planes
    attn_kernel<<<dim3(SSEQ, NHEAD), 128>>>();

    // 7) att = ctx @ out_w^T + out_b -> hi/lo planes
    gemm_mma<2,2><<<dim3(768/128, MROWS/128), 256, SMEM2>>>(
        chi, clo, whi+OFF_OW, out_b, nullptr, ohi, olo, 768);

    // 8) h = relu(att @ w1^T + b1)
    gemm_mma<1,2><<<dim3(384/128, MROWS/128), 256, SMEM2>>>(
        ohi, olo, whi+OFF_W1, b1, hb, nullptr, nullptr, 384);

    // 9) prob per row, 10) broadcast
    prob_compute<<<MROWS/8, 256>>>(hb, w2, b2, pb);
    bcast<<<MROWS/2, 256>>>(pb, out);
}

// round 9
// speedup vs baseline: 2.3486x; 1.2524x over previous
#include <cuda_runtime.h>
#include <cuda_fp16.h>
#include <math.h>
#include <stdint.h>

#define BBATCH 16
#define SSEQ   2048
#define EMB    768
#define NHEAD  8
#define DHEAD  96
#define MROWS  (BBATCH*SSEQ)   // 32768
#define KDIM   768
#define NCH1   12              // 768 / 64  (1-pass kernel, BK=64)
#define NCH2   24              // 768 / 32  (2-pass kernel, BK=32)

// ---------------- scratch (device globals; allocation-free rule) -----------
__device__ float   g_qkv[(size_t)MROWS*2304];
__device__ __half  g_fhi[(size_t)MROWS*KDIM];
__device__ __half  g_chi[(size_t)MROWS*KDIM];
__device__ __half  g_ohi[(size_t)MROWS*KDIM];
__device__ __half  g_olo[(size_t)MROWS*KDIM];
__device__ float   g_hbuf[(size_t)MROWS*384];
__device__ float   g_prob[(size_t)MROWS];
__device__ __half  g_whi[(size_t)(2304+768+384)*KDIM];

// ---------------- helpers ---------------------------------------------------
__device__ __forceinline__ uint32_t s2u(const void* p){
    uint32_t a;
    asm("{ .reg .u64 t; cvta.to.shared.u64 t, %1; cvt.u32.u64 %0, t; }":"=r"(a):"l"(p));
    return a;
}
#define SWZ(o)   ((o) ^ (((o) >> 3) & 0x70))
#define CP16(s, g) asm volatile("cp.async.cg.shared.global [%0], [%1], 16;"::"r"(s),"l"(g):"memory")

__device__ __forceinline__ void mma16816(float* c, const uint32_t* a, uint32_t b0, uint32_t b1){
    asm volatile("mma.sync.aligned.m16n8k16.row.col.f32.f16.f16.f32 "
        "{%0,%1,%2,%3},{%4,%5,%6,%7},{%8,%9},{%0,%1,%2,%3};"
        : "+f"(c[0]), "+f"(c[1]), "+f"(c[2]), "+f"(c[3])
        : "r"(a[0]), "r"(a[1]), "r"(a[2]), "r"(a[3]), "r"(b0), "r"(b1));
}

__device__ __forceinline__ void split_one(float x, __half& h, __half& l){
    h = __float2half(x);
    l = __float2half(x - __half2float(h));
}

// ---------------- fp32 -> fp16 convert (hi only), vectorized x4 ------------
__global__ __launch_bounds__(256)
void conv4(const float* __restrict__ src, __half* __restrict__ hi, size_t n4){
    size_t i = (size_t)blockIdx.x * blockDim.x + threadIdx.x;
    if (i >= n4) return;
    float4 v = ((const float4*)src)[i];
    ((__half2*)hi)[2*i]   = __halves2half2(__float2half(v.x), __float2half(v.y));
    ((__half2*)hi)[2*i+1] = __halves2half2(__float2half(v.z), __float2half(v.w));
}

__global__ __launch_bounds__(256)
void conv4x2(const float* __restrict__ sa, __half* __restrict__ ha, size_t na4,
             const float* __restrict__ sb, __half* __restrict__ hb, size_t nb4){
    size_t i = (size_t)blockIdx.x * blockDim.x + threadIdx.x;
    const float* src; __half* hi;
    if (i < na4){ src = sa; hi = ha; }
    else if (i < na4 + nb4){ i -= na4; src = sb; hi = hb; }
    else return;
    float4 v = ((const float4*)src)[i];
    ((__half2*)hi)[2*i]   = __halves2half2(__float2half(v.x), __float2half(v.y));
    ((__half2*)hi)[2*i+1] = __halves2half2(__float2half(v.z), __float2half(v.w));
}

// ---------------- 1-pass GEMM: C = Ahi @ Bhi^T + bias, BK=64 ---------------
// CTA 128x128, 256 thr, occ 2. Stage: A 128x128B + B 128x128B (SW128) = 32KB,
// 3-stage cp.async ring. EPI: 0 fp32 out, 2 fp16 hi/lo planes out.
template<int EPI>
__global__ __launch_bounds__(256, 2)
void gemm_1p(const __half* __restrict__ Ahi, const __half* __restrict__ Bhi,
             const float* __restrict__ bias, float* __restrict__ Cf,
             __half* __restrict__ Chi, __half* __restrict__ Clo, int N)
{
    extern __shared__ __align__(1024) char sm[];
    constexpr uint32_t STGB = 32768u;
    const int tid = threadIdx.x, lane = tid & 31, warp = tid >> 5;
    const int m0 = blockIdx.y * 128, n0 = blockIdx.x * 128;
    const int wm = (warp & 1) * 64, wn = (warp >> 1) * 32;
    const uint32_t sbase = s2u(sm);

    auto load_tile = [&](int t){
        const uint32_t st = sbase + (uint32_t)(t % 3) * STGB;
        const int k0 = t * 64;
        #pragma unroll
        for (int i = 0; i < 4; i++){                  // A: 1024 granules
            int g = tid + i * 256;
            int row = g >> 3, gg = g & 7;
            uint32_t d = SWZ((uint32_t)(row * 128 + gg * 16));
            CP16(st + d, Ahi + (size_t)(m0 + row) * KDIM + k0 + gg * 8);
        }
        #pragma unroll
        for (int i = 0; i < 4; i++){                  // B: 1024 granules
            int g = tid + i * 256;
            int row = g >> 3, gg = g & 7;
            uint32_t d = SWZ((uint32_t)(row * 128 + gg * 16));
            CP16(st + 16384u + d, Bhi + (size_t)(n0 + row) * KDIM + k0 + gg * 8);
        }
        asm volatile("cp.async.commit_group;" ::: "memory");
    };

    float acc[4][4][4];
    #pragma unroll
    for (int mi = 0; mi < 4; mi++)
        #pragma unroll
        for (int ni = 0; ni < 4; ni++)
            #pragma unroll
            for (int r = 0; r < 4; r++) acc[mi][ni][r] = 0.0f;

    load_tile(0);
    load_tile(1);

    const uint32_t aRow = (uint32_t)(lane & 15);
    const uint32_t aCol = (uint32_t)(lane >> 4) * 16u;
    const uint32_t bRow = (uint32_t)(((lane >> 4) & 1) * 8 + (lane & 7));
    const uint32_t bCol = (uint32_t)((lane >> 3) & 1) * 16u;

    #pragma unroll 1
    for (int t = 0; t < NCH1; t++){
        if (t < NCH1 - 1) asm volatile("cp.async.wait_group 1;" ::: "memory");
        else              asm volatile("cp.async.wait_group 0;" ::: "memory");
        __syncthreads();
        if (t + 2 < NCH1) load_tile(t + 2);

        const uint32_t sA = sbase + (uint32_t)(t % 3) * STGB;
        const uint32_t sB = sA + 16384u;

        #pragma unroll
        for (int kk = 0; kk < 4; kk++){               // 4 ksteps of 16
            const uint32_t kb = (uint32_t)kk * 32u;
            uint32_t a[4][4], bh[8];
            #pragma unroll
            for (int np = 0; np < 2; np++){
                uint32_t ad = sB + SWZ((uint32_t)((wn + np*16 + bRow) * 128) + kb + bCol);
                asm volatile("ldmatrix.sync.aligned.m8n8.x4.shared.b16 {%0,%1,%2,%3},[%4];"
                    : "=r"(bh[np*4]), "=r"(bh[np*4+1]), "=r"(bh[np*4+2]), "=r"(bh[np*4+3]) : "r"(ad));
            }
            #pragma unroll
            for (int mi = 0; mi < 4; mi++){
                uint32_t ad = sA + SWZ((uint32_t)((wm + mi*16 + aRow) * 128) + kb + aCol);
                asm volatile("ldmatrix.sync.aligned.m8n8.x4.shared.b16 {%0,%1,%2,%3},[%4];"
                    : "=r"(a[mi][0]), "=r"(a[mi][1]), "=r"(a[mi][2]), "=r"(a[mi][3]) : "r"(ad));
            }
            #pragma unroll
            for (int mi = 0; mi < 4; mi++)
                #pragma unroll
                for (int ni = 0; ni < 4; ni++)
                    mma16816(acc[mi][ni], a[mi], bh[(ni>>1)*4 + (ni&1)*2], bh[(ni>>1)*4 + (ni&1)*2 + 1]);
        }
    }

    const int erow = lane >> 2;
    const int ecol = (lane & 3) * 2;
    #pragma unroll
    for (int mi = 0; mi < 4; mi++){
        #pragma unroll
        for (int ni = 0; ni < 4; ni++){
            const int row = m0 + wm + mi * 16 + erow;
            const int col = n0 + wn + ni * 8 + ecol;
            const float b0 = bias[col], b1 = bias[col + 1];
            float v0 = acc[mi][ni][0] + b0, v1 = acc[mi][ni][1] + b1;
            float v2 = acc[mi][ni][2] + b0, v3 = acc[mi][ni][3] + b1;
            if (EPI == 2){
                __half h0,h1,h2,h3,l0,l1,l2,l3;
                split_one(v0,h0,l0); split_one(v1,h1,l1);
                split_one(v2,h2,l2); split_one(v3,h3,l3);
                *(__half2*)(Chi + (size_t)row * N + col)       = __halves2half2(h0, h1);
                *(__half2*)(Clo + (size_t)row * N + col)       = __halves2half2(l0, l1);
                *(__half2*)(Chi + (size_t)(row + 8) * N + col) = __halves2half2(h2, h3);
                *(__half2*)(Clo + (size_t)(row + 8) * N + col) = __halves2half2(l2, l3);
            } else {
                *(float2*)(Cf + (size_t)row * N + col)       = make_float2(v0, v1);
                *(float2*)(Cf + (size_t)(row + 8) * N + col) = make_float2(v2, v3);
            }
        }
    }
}

// ---------------- 2-pass GEMM: C = (Ahi+Alo) @ Bhi^T + bias, BK=32 ---------
// (used for gemm3 where A = attn_out hi/lo). EPI 1 = fp32 + ReLU.
#define SWZ64(o) ((o) ^ (((o) >> 3) & 0x30))
__global__ __launch_bounds__(256, 2)
void gemm_2p(const __half* __restrict__ Ahi, const __half* __restrict__ Alo,
             const __half* __restrict__ Bhi, const float* __restrict__ bias,
             float* __restrict__ Cf, int N)
{
    extern __shared__ __align__(1024) char sm[];
    constexpr uint32_t BOFF = 16384u, STGB = 24576u;
    const int tid = threadIdx.x, lane = tid & 31, warp = tid >> 5;
    const int m0 = blockIdx.y * 128, n0 = blockIdx.x * 128;
    const int wm = (warp & 1) * 64, wn = (warp >> 1) * 32;
    const uint32_t sbase = s2u(sm);

    auto load_tile = [&](int t){
        const uint32_t st = sbase + (uint32_t)(t % 3) * STGB;
        const int k0 = t * 32;
        #pragma unroll
        for (int i = 0; i < 4; i++){                  // A hi+lo
            int g = tid + i * 256;
            int row = g >> 3, slot = g & 7;
            int pl = slot >> 2, gg = slot & 3;
            uint32_t d = SWZ((uint32_t)(row * 128 + pl * 64 + gg * 16));
            const __half* src = (pl ? Alo : Ahi) + (size_t)(m0 + row) * KDIM + k0 + gg * 8;
            CP16(st + d, src);
        }
        #pragma unroll
        for (int i = 0; i < 2; i++){                  // B hi
            int g = tid + i * 256;
            int row = g >> 2, gg = g & 3;
            uint32_t d = SWZ64((uint32_t)(row * 64 + gg * 16));
            CP16(st + BOFF + d, Bhi + (size_t)(n0 + row) * KDIM + k0 + gg * 8);
        }
        asm volatile("cp.async.commit_group;" ::: "memory");
    };

    float acc[4][4][4];
    #pragma unroll
    for (int mi = 0; mi < 4; mi++)
        #pragma unroll
        for (int ni = 0; ni < 4; ni++)
            #pragma unroll
            for (int r = 0; r < 4; r++) acc[mi][ni][r] = 0.0f;

    load_tile(0);
    load_tile(1);

    const uint32_t aRow = (uint32_t)(lane & 15);
    const uint32_t aCol = (uint32_t)(lane >> 4) * 16u;
    const uint32_t bRow = (uint32_t)(((lane >> 4) & 1) * 8 + (lane & 7));
    const uint32_t bCol = (uint32_t)((lane >> 3) & 1) * 16u;

    #pragma unroll 1
    for (int t = 0; t < NCH2; t++){
        if (t < NCH2 - 1) asm volatile("cp.async.wait_group 1;" ::: "memory");
        else              asm volatile("cp.async.wait_group 0;" ::: "memory");
        __syncthreads();
        if (t + 2 < NCH2) load_tile(t + 2);

        const uint32_t sA = sbase + (uint32_t)(t % 3) * STGB;
        const uint32_t sB = sA + BOFF;

        #pragma unroll
        for (int kk = 0; kk < 2; kk++){
            const uint32_t kb = (uint32_t)kk * 32u;
            uint32_t a[4][4], bh[8];
            #pragma unroll
            for (int np = 0; np < 2; np++){
                uint32_t ad = sB + SWZ64((uint32_t)((wn + np*16 + bRow) * 64) + kb + bCol);
                asm volatile("ldmatrix.sync.aligned.m8n8.x4.shared.b16 {%0,%1,%2,%3},[%4];"
                    : "=r"(bh[np*4]), "=r"(bh[np*4+1]), "=r"(bh[np*4+2]), "=r"(bh[np*4+3]) : "r"(ad));
            }
            #pragma unroll
            for (int mi = 0; mi < 4; mi++){
                uint32_t ad = sA + SWZ((uint32_t)((wm + mi*16 + aRow) * 128) + kb + aCol);
                asm volatile("ldmatrix.sync.aligned.m8n8.x4.shared.b16 {%0,%1,%2,%3},[%4];"
                    : "=r"(a[mi][0]), "=r"(a[mi][1]), "=r"(a[mi][2]), "=r"(a[mi][3]) : "r"(ad));
            }
            #pragma unroll
            for (int mi = 0; mi < 4; mi++)
                #pragma unroll
                for (int ni = 0; ni < 4; ni++)
                    mma16816(acc[mi][ni], a[mi], bh[(ni>>1)*4 + (ni&1)*2], bh[(ni>>1)*4 + (ni&1)*2 + 1]);
            #pragma unroll
            for (int mi = 0; mi < 4; mi++){           // A lo
                uint32_t ad = sA + SWZ((uint32_t)((wm + mi*16 + aRow) * 128) + 64u + kb + aCol);
                asm volatile("ldmatrix.sync.aligned.m8n8.x4.shared.b16 {%0,%1,%2,%3},[%4];"
                    : "=r"(a[mi][0]), "=r"(a[mi][1]), "=r"(a[mi][2]), "=r"(a[mi][3]) : "r"(ad));
            }
            #pragma unroll
            for (int mi = 0; mi < 4; mi++)
                #pragma unroll
                for (int ni = 0; ni < 4; ni++)
                    mma16816(acc[mi][ni], a[mi], bh[(ni>>1)*4 + (ni&1)*2], bh[(ni>>1)*4 + (ni&1)*2 + 1]);
        }
    }

    const int erow = lane >> 2;
    const int ecol = (lane & 3) * 2;
    #pragma unroll
    for (int mi = 0; mi < 4; mi++){
        #pragma unroll
        for (int ni = 0; ni < 4; ni++){
            const int row = m0 + wm + mi * 16 + erow;
            const int col = n0 + wn + ni * 8 + ecol;
            const float b0 = bias[col], b1 = bias[col + 1];
            float v0 = fmaxf(acc[mi][ni][0] + b0, 0.f);
            float v1 = fmaxf(acc[mi][ni][1] + b1, 0.f);
            float v2 = fmaxf(acc[mi][ni][2] + b0, 0.f);
            float v3 = fmaxf(acc[mi][ni][3] + b1, 0.f);
            *(float2*)(Cf + (size_t)row * N + col)       = make_float2(v0, v1);
            *(float2*)(Cf + (size_t)(row + 8) * N + col) = make_float2(v2, v3);
        }
    }
}

// ---------------- attention over axis-0 (16) per (s,h), vectorized ---------
__global__ __launch_bounds__(128)
void attn_kernel(){
    const int s = blockIdx.x, h = blockIdx.y, tid = threadIdx.x;
    __shared__ float q[16][100], k[16][100], v[16][100];
    __shared__ float sc[16][17];

    const float* srcbase = g_qkv + (size_t)s*2304 + h*DHEAD;
    #pragma unroll
    for (int i = 0; i < 3; i++){
        int g = tid + i * 128;
        int l = g / 24, c = g % 24;
        const float* p = srcbase + (size_t)l * ((size_t)SSEQ * 2304) + c * 4;
        *(float4*)&q[l][c*4] = *(const float4*)(p);
        *(float4*)&k[l][c*4] = *(const float4*)(p + 768);
        *(float4*)&v[l][c*4] = *(const float4*)(p + 1536);
    }
    __syncthreads();

    const float scale = rsqrtf((float)DHEAD);
    #pragma unroll
    for (int i = 0; i < 2; i++){
        int idx = tid + i * 128;
        int l = idx >> 4, m = idx & 15;
        float acc = 0.f;
        #pragma unroll
        for (int d = 0; d < DHEAD; d++) acc = fmaf(q[l][d], k[m][d], acc);
        sc[l][m] = acc * scale;
    }
    __syncthreads();

    if (tid < 16){
        float mx = -INFINITY;
        #pragma unroll
        for (int m = 0; m < 16; m++) mx = fmaxf(mx, sc[tid][m]);
        float sum = 0.f;
        #pragma unroll
        for (int m = 0; m < 16; m++){ float e = expf(sc[tid][m]-mx); sc[tid][m]=e; sum+=e; }
        float inv = 1.f/sum;
        #pragma unroll
        for (int m = 0; m < 16; m++) sc[tid][m] *= inv;
    }
    __syncthreads();

    #pragma unroll
    for (int i = 0; i < 6; i++){
        int idx = tid + i * 128;
        int l = idx / 48, dp = idx % 48;
        int d = dp * 2;
        float a0 = 0.f, a1 = 0.f;
        #pragma unroll
        for (int m = 0; m < 16; m++){
            float w = sc[l][m];
            a0 = fmaf(w, v[m][d],   a0);
            a1 = fmaf(w, v[m][d+1], a1);
        }
        size_t o = ((size_t)l*SSEQ + s)*EMB + h*DHEAD + d;
        *(__half2*)(g_chi + o) = __halves2half2(__float2half(a0), __float2half(a1));
    }
}

// ---------------- prob: one warp per row, shuffle reduction ----------------
__global__ __launch_bounds__(256)
void prob_compute(const float* __restrict__ hbuf, const float* __restrict__ w2,
                  const float* __restrict__ b2, float* __restrict__ probs){
    const int gw = (blockIdx.x * 256 + threadIdx.x) >> 5;
    const int lane = threadIdx.x & 31;
    if (gw >= MROWS) return;
    const float4* row4 = (const float4*)(hbuf + (size_t)gw * 384);
    const float4* w4   = (const float4*)w2;
    float p = 0.f;
    #pragma unroll
    for (int j = 0; j < 3; j++){
        float4 a = row4[lane + j*32];
        float4 w = w4[lane + j*32];
        p = fmaf(a.x, w.x, p); p = fmaf(a.y, w.y, p);
        p = fmaf(a.z, w.z, p); p = fmaf(a.w, w.w, p);
    }
    #pragma unroll
    for (int o = 16; o > 0; o >>= 1) p += __shfl_xor_sync(0xFFFFFFFFu, p, o);
    if (lane == 0) probs[gw] = p + b2[0];
}

// ---------------- broadcast: out[r,:] = probs[r] ----------------------------
__global__ __launch_bounds__(256)
void bcast(const float* __restrict__ probs, float* __restrict__ out){
    const int r = blockIdx.x * 2 + (threadIdx.x >> 7);
    const int t = threadIdx.x & 127;
    const float pv = probs[r];
    float4 p4 = make_float4(pv, pv, pv, pv);
    float4* orow = (float4*)(out + (size_t)r * SSEQ);
    #pragma unroll
    for (int i = 0; i < 4; i++) orow[t + i*128] = p4;
}

// ---------------------------------------------------------------------------
extern "C" void kernel_launch(void* const* d_in, const int* in_sizes, int n_in,
                              void* d_out, int out_size){
    const float* features = (const float*)d_in[0];
    const float* in_w  = (const float*)d_in[1];
    const float* in_b  = (const float*)d_in[2];
    const float* out_w = (const float*)d_in[3];
    const float* out_b = (const float*)d_in[4];
    const float* w1    = (const float*)d_in[5];
    const float* b1    = (const float*)d_in[6];
    const float* w2    = (const float*)d_in[7];
    const float* b2    = (const float*)d_in[8];
    float* out = (float*)d_out;

    float *qkv, *hb, *pb;
    __half *fhi,*chi,*ohi,*olo,*whi;
    cudaGetSymbolAddress((void**)&qkv, g_qkv);
    cudaGetSymbolAddress((void**)&hb,  g_hbuf);
    cudaGetSymbolAddress((void**)&pb,  g_prob);
    cudaGetSymbolAddress((void**)&fhi, g_fhi);
    cudaGetSymbolAddress((void**)&chi, g_chi);
    cudaGetSymbolAddress((void**)&ohi, g_ohi);
    cudaGetSymbolAddress((void**)&olo, g_olo);
    cudaGetSymbolAddress((void**)&whi, g_whi);

    const size_t OFF_V  = (size_t)1536*KDIM;
    const size_t OFF_OW = (size_t)2304*KDIM;
    const size_t OFF_W1 = (size_t)(2304+768)*KDIM;

    const int SMEM1 = 3 * 32768;   // 1-pass BK=64 ring
    const int SMEM2 = 3 * 24576;   // 2-pass BK=32 ring
    cudaFuncSetAttribute(gemm_1p<0>, cudaFuncAttributeMaxDynamicSharedMemorySize, SMEM1);
    cudaFuncSetAttribute(gemm_1p<2>, cudaFuncAttributeMaxDynamicSharedMemorySize, SMEM1);
    cudaFuncSetAttribute(gemm_2p,    cudaFuncAttributeMaxDynamicSharedMemorySize, SMEM2);

    // launches 1-3: converts (keeps QK gemm in profiled slot #4)
    {
        size_t n4 = (size_t)MROWS*KDIM/4;
        conv4<<<(unsigned)((n4+255)/256), 256>>>(features, fhi, n4);
        n4 = (size_t)2304*KDIM/4;
        conv4<<<(unsigned)((n4+255)/256), 256>>>(in_w, whi, n4);
        size_t na4 = (size_t)768*KDIM/4, nb4 = (size_t)384*KDIM/4;
        conv4x2<<<(unsigned)((na4+nb4+255)/256), 256>>>(
            out_w, whi+OFF_OW, na4, w1, whi+OFF_W1, nb4);
    }

    // 4) QK = features @ in_w[0:1536]^T + b   (1-pass)
    gemm_1p<0><<<dim3(1536/128, MROWS/128), 256, SMEM1>>>(
        fhi, whi, in_b, qkv, nullptr, nullptr, 2304);

    // 5) V = features @ in_w[1536:2304]^T + b (1-pass)
    gemm_1p<0><<<dim3(768/128, MROWS/128), 256, SMEM1>>>(
        fhi, whi + OFF_V, in_b + 1536, qkv + 1536, nullptr, nullptr, 2304);

    // 6) attention -> ctx (fp16 hi only)
    attn_kernel<<<dim3(SSEQ, NHEAD), 128>>>();

    // 7) att = ctx @ out_w^T + out_b -> fp16 hi/lo planes (1-pass)
    gemm_1p<2><<<dim3(768/128, MROWS/128), 256, SMEM1>>>(
        chi, whi+OFF_OW, out_b, nullptr, ohi, olo, 768);

    // 8) h = relu(att @ w1^T + b1)  (2-pass: A = attn_out hi/lo)
    gemm_2p<<<dim3(384/128, MROWS/128), 256, SMEM2>>>(
        ohi, olo, whi+OFF_W1, b1, hb, 384);

    // 9) prob per row, 10) broadcast
    prob_compute<<<MROWS/8, 256>>>(hb, w2, b2, pb);
    bcast<<<MROWS/2, 256>>>(pb, out);
}

// round 10
// speedup vs baseline: 2.4415x; 1.0395x over previous
#include <cuda_runtime.h>
#include <cuda_fp16.h>
#include <math.h>
#include <stdint.h>

#define BBATCH 16
#define SSEQ   2048
#define EMB    768
#define NHEAD  8
#define DHEAD  96
#define MROWS  (BBATCH*SSEQ)   // 32768
#define KDIM   768
#define NCH1   12              // 768 / 64  (1-pass, BK=64)
#define NCH2   24              // 768 / 32  (2-pass, BK=32)

// ---------------- scratch (device globals; allocation-free rule) -----------
__device__ float   g_qkv[(size_t)MROWS*2304];
__device__ __half  g_fhi[(size_t)MROWS*KDIM];
__device__ __half  g_chi[(size_t)MROWS*KDIM];
__device__ __half  g_ohi[(size_t)MROWS*KDIM];
__device__ __half  g_olo[(size_t)MROWS*KDIM];
__device__ float   g_part[(size_t)MROWS*12];
__device__ __half  g_whi[(size_t)(2304+768+384)*KDIM];

// ---------------- helpers ---------------------------------------------------
__device__ __forceinline__ uint32_t s2u(const void* p){
    uint32_t a;
    asm("{ .reg .u64 t; cvta.to.shared.u64 t, %1; cvt.u32.u64 %0, t; }":"=r"(a):"l"(p));
    return a;
}
#define SWZ(o)   ((o) ^ (((o) >> 3) & 0x70))
#define SWZ64(o) ((o) ^ (((o) >> 3) & 0x30))
#define CP16(s, g) asm volatile("cp.async.cg.shared.global [%0], [%1], 16;"::"r"(s),"l"(g):"memory")

__device__ __forceinline__ void mma16816(float* c, const uint32_t* a, uint32_t b0, uint32_t b1){
    asm volatile("mma.sync.aligned.m16n8k16.row.col.f32.f16.f16.f32 "
        "{%0,%1,%2,%3},{%4,%5,%6,%7},{%8,%9},{%0,%1,%2,%3};"
        : "+f"(c[0]), "+f"(c[1]), "+f"(c[2]), "+f"(c[3])
        : "r"(a[0]), "r"(a[1]), "r"(a[2]), "r"(a[3]), "r"(b0), "r"(b1));
}

__device__ __forceinline__ void split_one(float x, __half& h, __half& l){
    h = __float2half(x);
    l = __float2half(x - __half2float(h));
}

// ---------------- fp32 -> fp16 convert, vectorized x4 ----------------------
__global__ __launch_bounds__(256)
void conv4(const float* __restrict__ src, __half* __restrict__ hi, size_t n4){
    size_t i = (size_t)blockIdx.x * blockDim.x + threadIdx.x;
    if (i >= n4) return;
    float4 v = ((const float4*)src)[i];
    ((__half2*)hi)[2*i]   = __halves2half2(__float2half(v.x), __float2half(v.y));
    ((__half2*)hi)[2*i+1] = __halves2half2(__float2half(v.z), __float2half(v.w));
}

__global__ __launch_bounds__(256)
void conv4x2(const float* __restrict__ sa, __half* __restrict__ ha, size_t na4,
             const float* __restrict__ sb, __half* __restrict__ hb, size_t nb4){
    size_t i = (size_t)blockIdx.x * blockDim.x + threadIdx.x;
    const float* src; __half* hi;
    if (i < na4){ src = sa; hi = ha; }
    else if (i < na4 + nb4){ i -= na4; src = sb; hi = hb; }
    else return;
    float4 v = ((const float4*)src)[i];
    ((__half2*)hi)[2*i]   = __halves2half2(__float2half(v.x), __float2half(v.y));
    ((__half2*)hi)[2*i+1] = __halves2half2(__float2half(v.z), __float2half(v.w));
}

// ---------------- 1-pass GEMM: C = Ahi @ Bhi^T + bias, BK=64 ---------------
// CTA 128x128, 256 thr, occ 2, 3-stage ring. EPI: 0 fp32, 2 fp16 hi/lo out.
template<int EPI>
__global__ __launch_bounds__(256, 2)
void gemm_1p(const __half* __restrict__ Ahi, const __half* __restrict__ Bhi,
             const float* __restrict__ bias, float* __restrict__ Cf,
             __half* __restrict__ Chi, __half* __restrict__ Clo, int N)
{
    extern __shared__ __align__(1024) char sm[];
    constexpr uint32_t STGB = 32768u;
    const int tid = threadIdx.x, lane = tid & 31, warp = tid >> 5;
    const int m0 = blockIdx.y * 128, n0 = blockIdx.x * 128;
    const int wm = (warp & 1) * 64, wn = (warp >> 1) * 32;
    const uint32_t sbase = s2u(sm);

    auto load_tile = [&](int t){
        const uint32_t st = sbase + (uint32_t)(t % 3) * STGB;
        const int k0 = t * 64;
        #pragma unroll
        for (int i = 0; i < 4; i++){
            int g = tid + i * 256;
            int row = g >> 3, gg = g & 7;
            uint32_t d = SWZ((uint32_t)(row * 128 + gg * 16));
            CP16(st + d, Ahi + (size_t)(m0 + row) * KDIM + k0 + gg * 8);
        }
        #pragma unroll
        for (int i = 0; i < 4; i++){
            int g = tid + i * 256;
            int row = g >> 3, gg = g & 7;
            uint32_t d = SWZ((uint32_t)(row * 128 + gg * 16));
            CP16(st + 16384u + d, Bhi + (size_t)(n0 + row) * KDIM + k0 + gg * 8);
        }
        asm volatile("cp.async.commit_group;" ::: "memory");
    };

    float acc[4][4][4];
    #pragma unroll
    for (int mi = 0; mi < 4; mi++)
        #pragma unroll
        for (int ni = 0; ni < 4; ni++)
            #pragma unroll
            for (int r = 0; r < 4; r++) acc[mi][ni][r] = 0.0f;

    load_tile(0);
    load_tile(1);

    const uint32_t aRow = (uint32_t)(lane & 15);
    const uint32_t aCol = (uint32_t)(lane >> 4) * 16u;
    const uint32_t bRow = (uint32_t)(((lane >> 4) & 1) * 8 + (lane & 7));
    const uint32_t bCol = (uint32_t)((lane >> 3) & 1) * 16u;

    #pragma unroll 1
    for (int t = 0; t < NCH1; t++){
        if (t < NCH1 - 1) asm volatile("cp.async.wait_group 1;" ::: "memory");
        else              asm volatile("cp.async.wait_group 0;" ::: "memory");
        __syncthreads();
        if (t + 2 < NCH1) load_tile(t + 2);

        const uint32_t sA = sbase + (uint32_t)(t % 3) * STGB;
        const uint32_t sB = sA + 16384u;

        #pragma unroll
        for (int kk = 0; kk < 4; kk++){
            const uint32_t kb = (uint32_t)kk * 32u;
            uint32_t a[4][4], bh[8];
            #pragma unroll
            for (int np = 0; np < 2; np++){
                uint32_t ad = sB + SWZ((uint32_t)((wn + np*16 + bRow) * 128) + kb + bCol);
                asm volatile("ldmatrix.sync.aligned.m8n8.x4.shared.b16 {%0,%1,%2,%3},[%4];"
                    : "=r"(bh[np*4]), "=r"(bh[np*4+1]), "=r"(bh[np*4+2]), "=r"(bh[np*4+3]) : "r"(ad));
            }
            #pragma unroll
            for (int mi = 0; mi < 4; mi++){
                uint32_t ad = sA + SWZ((uint32_t)((wm + mi*16 + aRow) * 128) + kb + aCol);
                asm volatile("ldmatrix.sync.aligned.m8n8.x4.shared.b16 {%0,%1,%2,%3},[%4];"
                    : "=r"(a[mi][0]), "=r"(a[mi][1]), "=r"(a[mi][2]), "=r"(a[mi][3]) : "r"(ad));
            }
            #pragma unroll
            for (int mi = 0; mi < 4; mi++)
                #pragma unroll
                for (int ni = 0; ni < 4; ni++)
                    mma16816(acc[mi][ni], a[mi], bh[(ni>>1)*4 + (ni&1)*2], bh[(ni>>1)*4 + (ni&1)*2 + 1]);
        }
    }

    const int erow = lane >> 2;
    const int ecol = (lane & 3) * 2;
    #pragma unroll
    for (int mi = 0; mi < 4; mi++){
        #pragma unroll
        for (int ni = 0; ni < 4; ni++){
            const int row = m0 + wm + mi * 16 + erow;
            const int col = n0 + wn + ni * 8 + ecol;
            const float b0 = bias[col], b1 = bias[col + 1];
            float v0 = acc[mi][ni][0] + b0, v1 = acc[mi][ni][1] + b1;
            float v2 = acc[mi][ni][2] + b0, v3 = acc[mi][ni][3] + b1;
            if (EPI == 2){
                __half h0,h1,h2,h3,l0,l1,l2,l3;
                split_one(v0,h0,l0); split_one(v1,h1,l1);
                split_one(v2,h2,l2); split_one(v3,h3,l3);
                *(__half2*)(Chi + (size_t)row * N + col)       = __halves2half2(h0, h1);
                *(__half2*)(Clo + (size_t)row * N + col)       = __halves2half2(l0, l1);
                *(__half2*)(Chi + (size_t)(row + 8) * N + col) = __halves2half2(h2, h3);
                *(__half2*)(Clo + (size_t)(row + 8) * N + col) = __halves2half2(l2, l3);
            } else {
                *(float2*)(Cf + (size_t)row * N + col)       = make_float2(v0, v1);
                *(float2*)(Cf + (size_t)(row + 8) * N + col) = make_float2(v2, v3);
            }
        }
    }
}

// ---------------- gemm3 fused: h=relu((Ahi+Alo)@W1^T+b1); partial dot w2 ----
// 2-pass, BK=32. Epilogue writes NO h: instead per-row partial dot products
// with w2 go to part[row*12 + bn*4 + (warp>>1)]  (deterministic, no atomics).
__global__ __launch_bounds__(256, 2)
void gemm_fused(const __half* __restrict__ Ahi, const __half* __restrict__ Alo,
                const __half* __restrict__ Bhi, const float* __restrict__ bias,
                const float* __restrict__ w2, float* __restrict__ part)
{
    extern __shared__ __align__(1024) char sm[];
    constexpr uint32_t BOFF = 16384u, STGB = 24576u;
    const int tid = threadIdx.x, lane = tid & 31, warp = tid >> 5;
    const int m0 = blockIdx.y * 128, n0 = blockIdx.x * 128;
    const int wm = (warp & 1) * 64, wn = (warp >> 1) * 32;
    const uint32_t sbase = s2u(sm);

    auto load_tile = [&](int t){
        const uint32_t st = sbase + (uint32_t)(t % 3) * STGB;
        const int k0 = t * 32;
        #pragma unroll
        for (int i = 0; i < 4; i++){
            int g = tid + i * 256;
            int row = g >> 3, slot = g & 7;
            int pl = slot >> 2, gg = slot & 3;
            uint32_t d = SWZ((uint32_t)(row * 128 + pl * 64 + gg * 16));
            const __half* src = (pl ? Alo : Ahi) + (size_t)(m0 + row) * KDIM + k0 + gg * 8;
            CP16(st + d, src);
        }
        #pragma unroll
        for (int i = 0; i < 2; i++){
            int g = tid + i * 256;
            int row = g >> 2, gg = g & 3;
            uint32_t d = SWZ64((uint32_t)(row * 64 + gg * 16));
            CP16(st + BOFF + d, Bhi + (size_t)(n0 + row) * KDIM + k0 + gg * 8);
        }
        asm volatile("cp.async.commit_group;" ::: "memory");
    };

    float acc[4][4][4];
    #pragma unroll
    for (int mi = 0; mi < 4; mi++)
        #pragma unroll
        for (int ni = 0; ni < 4; ni++)
            #pragma unroll
            for (int r = 0; r < 4; r++) acc[mi][ni][r] = 0.0f;

    load_tile(0);
    load_tile(1);

    const uint32_t aRow = (uint32_t)(lane & 15);
    const uint32_t aCol = (uint32_t)(lane >> 4) * 16u;
    const uint32_t bRow = (uint32_t)(((lane >> 4) & 1) * 8 + (lane & 7));
    const uint32_t bCol = (uint32_t)((lane >> 3) & 1) * 16u;

    #pragma unroll 1
    for (int t = 0; t < NCH2; t++){
        if (t < NCH2 - 1) asm volatile("cp.async.wait_group 1;" ::: "memory");
        else              asm volatile("cp.async.wait_group 0;" ::: "memory");
        __syncthreads();
        if (t + 2 < NCH2) load_tile(t + 2);

        const uint32_t sA = sbase + (uint32_t)(t % 3) * STGB;
        const uint32_t sB = sA + BOFF;

        #pragma unroll
        for (int kk = 0; kk < 2; kk++){
            const uint32_t kb = (uint32_t)kk * 32u;
            uint32_t a[4][4], bh[8];
            #pragma unroll
            for (int np = 0; np < 2; np++){
                uint32_t ad = sB + SWZ64((uint32_t)((wn + np*16 + bRow) * 64) + kb + bCol);
                asm volatile("ldmatrix.sync.aligned.m8n8.x4.shared.b16 {%0,%1,%2,%3},[%4];"
                    : "=r"(bh[np*4]), "=r"(bh[np*4+1]), "=r"(bh[np*4+2]), "=r"(bh[np*4+3]) : "r"(ad));
            }
            #pragma unroll
            for (int mi = 0; mi < 4; mi++){
                uint32_t ad = sA + SWZ((uint32_t)((wm + mi*16 + aRow) * 128) + kb + aCol);
                asm volatile("ldmatrix.sync.aligned.m8n8.x4.shared.b16 {%0,%1,%2,%3},[%4];"
                    : "=r"(a[mi][0]), "=r"(a[mi][1]), "=r"(a[mi][2]), "=r"(a[mi][3]) : "r"(ad));
            }
            #pragma unroll
            for (int mi = 0; mi < 4; mi++)
                #pragma unroll
                for (int ni = 0; ni < 4; ni++)
                    mma16816(acc[mi][ni], a[mi], bh[(ni>>1)*4 + (ni&1)*2], bh[(ni>>1)*4 + (ni&1)*2 + 1]);
            #pragma unroll
            for (int mi = 0; mi < 4; mi++){
                uint32_t ad = sA + SWZ((uint32_t)((wm + mi*16 + aRow) * 128) + 64u + kb + aCol);
                asm volatile("ldmatrix.sync.aligned.m8n8.x4.shared.b16 {%0,%1,%2,%3},[%4];"
                    : "=r"(a[mi][0]), "=r"(a[mi][1]), "=r"(a[mi][2]), "=r"(a[mi][3]) : "r"(ad));
            }
            #pragma unroll
            for (int mi = 0; mi < 4; mi++)
                #pragma unroll
                for (int ni = 0; ni < 4; ni++)
                    mma16816(acc[mi][ni], a[mi], bh[(ni>>1)*4 + (ni&1)*2], bh[(ni>>1)*4 + (ni&1)*2 + 1]);
        }
    }

    // epilogue: bias + relu + dot(w2 slice) -> per-row partials
    const int erow = lane >> 2;
    const int ecol = (lane & 3) * 2;
    const int slot = blockIdx.x * 4 + (warp >> 1);      // 0..11
    #pragma unroll
    for (int mi = 0; mi < 4; mi++){
        float rs0 = 0.f, rs1 = 0.f;                      // row, row+8
        #pragma unroll
        for (int ni = 0; ni < 4; ni++){
            const int col = n0 + wn + ni * 8 + ecol;
            const float b0 = bias[col], b1 = bias[col + 1];
            const float w0 = w2[col],   w1 = w2[col + 1];
            rs0 += fmaxf(acc[mi][ni][0] + b0, 0.f) * w0
                 + fmaxf(acc[mi][ni][1] + b1, 0.f) * w1;
            rs1 += fmaxf(acc[mi][ni][2] + b0, 0.f) * w0
                 + fmaxf(acc[mi][ni][3] + b1, 0.f) * w1;
        }
        rs0 += __shfl_xor_sync(0xFFFFFFFFu, rs0, 1);
        rs0 += __shfl_xor_sync(0xFFFFFFFFu, rs0, 2);
        rs1 += __shfl_xor_sync(0xFFFFFFFFu, rs1, 1);
        rs1 += __shfl_xor_sync(0xFFFFFFFFu, rs1, 2);
        if ((lane & 3) == 0){
            const int row = m0 + wm + mi * 16 + erow;
            part[(size_t)row * 12 + slot]       = rs0;
            part[(size_t)(row + 8) * 12 + slot] = rs1;
        }
    }
}

// ---------------- attention over axis-0 (16) per (s,h), vectorized ---------
__global__ __launch_bounds__(128)
void attn_kernel(){
    const int s = blockIdx.x, h = blockIdx.y, tid = threadIdx.x;
    __shared__ float q[16][100], k[16][100], v[16][100];
    __shared__ float sc[16][17];

    const float* srcbase = g_qkv + (size_t)s*2304 + h*DHEAD;
    #pragma unroll
    for (int i = 0; i < 3; i++){
        int g = tid + i * 128;
        int l = g / 24, c = g % 24;
        const float* p = srcbase + (size_t)l * ((size_t)SSEQ * 2304) + c * 4;
        *(float4*)&q[l][c*4] = *(const float4*)(p);
        *(float4*)&k[l][c*4] = *(const float4*)(p + 768);
        *(float4*)&v[l][c*4] = *(const float4*)(p + 1536);
    }
    __syncthreads();

    const float scale = rsqrtf((float)DHEAD);
    #pragma unroll
    for (int i = 0; i < 2; i++){
        int idx = tid + i * 128;
        int l = idx >> 4, m = idx & 15;
        float acc = 0.f;
        #pragma unroll
        for (int d = 0; d < DHEAD; d++) acc = fmaf(q[l][d], k[m][d], acc);
        sc[l][m] = acc * scale;
    }
    __syncthreads();

    if (tid < 16){
        float mx = -INFINITY;
        #pragma unroll
        for (int m = 0; m < 16; m++) mx = fmaxf(mx, sc[tid][m]);
        float sum = 0.f;
        #pragma unroll
        for (int m = 0; m < 16; m++){ float e = expf(sc[tid][m]-mx); sc[tid][m]=e; sum+=e; }
        float inv = 1.f/sum;
        #pragma unroll
        for (int m = 0; m < 16; m++) sc[tid][m] *= inv;
    }
    __syncthreads();

    #pragma unroll
    for (int i = 0; i < 6; i++){
        int idx = tid + i * 128;
        int l = idx / 48, dp = idx % 48;
        int d = dp * 2;
        float a0 = 0.f, a1 = 0.f;
        #pragma unroll
        for (int m = 0; m < 16; m++){
            float w = sc[l][m];
            a0 = fmaf(w, v[m][d],   a0);
            a1 = fmaf(w, v[m][d+1], a1);
        }
        size_t o = ((size_t)l*SSEQ + s)*EMB + h*DHEAD + d;
        *(__half2*)(g_chi + o) = __halves2half2(__float2half(a0), __float2half(a1));
    }
}

// ---------------- broadcast: out[r,:] = sum(part[r]) + b2 -------------------
__global__ __launch_bounds__(256)
void bcast(const float* __restrict__ part, const float* __restrict__ b2,
           float* __restrict__ out){
    const int r = blockIdx.x * 2 + (threadIdx.x >> 7);
    const int t = threadIdx.x & 127;
    float p = b2[0];
    #pragma unroll
    for (int s = 0; s < 12; s++) p += part[(size_t)r * 12 + s];
    float4 p4 = make_float4(p, p, p, p);
    float4* orow = (float4*)(out + (size_t)r * SSEQ);
    #pragma unroll
    for (int i = 0; i < 4; i++) orow[t + i*128] = p4;
}

// ---------------------------------------------------------------------------
extern "C" void kernel_launch(void* const* d_in, const int* in_sizes, int n_in,
                              void* d_out, int out_size){
    const float* features = (const float*)d_in[0];
    const float* in_w  = (const float*)d_in[1];
    const float* in_b  = (const float*)d_in[2];
    const float* out_w = (const float*)d_in[3];
    const float* out_b = (const float*)d_in[4];
    const float* w1    = (const float*)d_in[5];
    const float* b1    = (const float*)d_in[6];
    const float* w2    = (const float*)d_in[7];
    const float* b2    = (const float*)d_in[8];
    float* out = (float*)d_out;

    float *qkv, *pt;
    __half *fhi,*chi,*ohi,*olo,*whi;
    cudaGetSymbolAddress((void**)&qkv, g_qkv);
    cudaGetSymbolAddress((void**)&pt,  g_part);
    cudaGetSymbolAddress((void**)&fhi, g_fhi);
    cudaGetSymbolAddress((void**)&chi, g_chi);
    cudaGetSymbolAddress((void**)&ohi, g_ohi);
    cudaGetSymbolAddress((void**)&olo, g_olo);
    cudaGetSymbolAddress((void**)&whi, g_whi);

    const size_t OFF_OW = (size_t)2304*KDIM;
    const size_t OFF_W1 = (size_t)(2304+768)*KDIM;

    const int SMEM1 = 3 * 32768;
    const int SMEM2 = 3 * 24576;
    cudaFuncSetAttribute(gemm_1p<0>, cudaFuncAttributeMaxDynamicSharedMemorySize, SMEM1);
    cudaFuncSetAttribute(gemm_1p<2>, cudaFuncAttributeMaxDynamicSharedMemorySize, SMEM1);
    cudaFuncSetAttribute(gemm_fused, cudaFuncAttributeMaxDynamicSharedMemorySize, SMEM2);

    // launches 1-3: converts (keeps QKV gemm in profiled slot #4)
    {
        size_t n4 = (size_t)MROWS*KDIM/4;
        conv4<<<(unsigned)((n4+255)/256), 256>>>(features, fhi, n4);
        n4 = (size_t)2304*KDIM/4;
        conv4<<<(unsigned)((n4+255)/256), 256>>>(in_w, whi, n4);
        size_t na4 = (size_t)768*KDIM/4, nb4 = (size_t)384*KDIM/4;
        conv4x2<<<(unsigned)((na4+nb4+255)/256), 256>>>(
            out_w, whi+OFF_OW, na4, w1, whi+OFF_W1, nb4);
    }

    // 4) QKV = features @ in_w^T + in_b   (single 1-pass GEMM, N=2304)
    gemm_1p<0><<<dim3(2304/128, MROWS/128), 256, SMEM1>>>(
        fhi, whi, in_b, qkv, nullptr, nullptr, 2304);

    // 5) attention -> ctx (fp16)
    attn_kernel<<<dim3(SSEQ, NHEAD), 128>>>();

    // 6) att = ctx @ out_w^T + out_b -> fp16 hi/lo planes (1-pass)
    gemm_1p<2><<<dim3(768/128, MROWS/128), 256, SMEM1>>>(
        chi, whi+OFF_OW, out_b, nullptr, ohi, olo, 768);

    // 7) fused: relu(att @ w1^T + b1) . w2  -> 12 partials per row
    gemm_fused<<<dim3(384/128, MROWS/128), 256, SMEM2>>>(
        ohi, olo, whi+OFF_W1, b1, w2, pt);

    // 8) broadcast (sums partials + b2)
    bcast<<<MROWS/2, 256>>>(pt, b2, out);
}